// round 12
// baseline (speedup 1.0000x reference)
#include <cuda_runtime.h>
#include <cuda_fp16.h>
#include <math.h>
#include <cstdint>

// Problem constants (fixed by setup_inputs)
#define B_     2
#define T_     2048
#define D_     1024
#define H_     16
#define HD_    64
#define TOK_   4096      // B*T
#define NCH_   64        // B*NC chunks
#define CH_    64        // chunk_size
#define KV_    256       // K*NL
#define KVTOK_ 16384     // NCH_*KV_
#define DFF_   4096

// ---------------- scratch (static device globals; no allocation) ----------------
__device__ __half g_h   [TOK_  * D_];      // LN out (GEMM A, half k16-perm)
__device__ __half g_kvln[KVTOK_* D_];
__device__ __half g_attn[TOK_  * D_];      // attention out (GEMM A)
__device__ __half g_ffn [TOK_  * DFF_];    // GELU out (GEMM A)
__device__ __half g_wt  [16u * 1024u * 1024u];  // transposed weights (GEMM B)
__device__ __half g_qk  [TOK_  * 2 * D_];  // SA q|k (half, k16-perm)
__device__ __half g_vt  [TOK_  * D_];      // SA V^T: [b][dim][token]
__device__ __half g_ccq [TOK_  * D_];      // CCA q (half perm)
__device__ __half g_cck [KVTOK_* D_];      // CCA k (half perm)
__device__ __half g_ccvt[KVTOK_* D_];      // CCA V^T: [chunk][dim][key]
__device__ float  g_x1  [TOK_  * D_];

// ---------------- helpers ---------------------------------------------------------
__device__ __forceinline__ uint32_t smem_u32(const void* p) {
    uint32_t a;
    asm("{ .reg .u64 t; cvta.to.shared.u64 t, %1; cvt.u32.u64 %0, t; }" : "=r"(a) : "l"(p));
    return a;
}

// k16 permutation: original col c -> packed pos (pairs (2t,2t+1),(2t+8,2t+9) adjacent)
__device__ __forceinline__ int p16(int c) {
    return (c & ~15) + 4 * ((c & 7) >> 1) + 2 * ((c >> 3) & 1) + (c & 1);
}

__device__ __forceinline__ void cp16(uint32_t s, const void* g) {
    asm volatile("cp.async.cg.shared.global [%0], [%1], 16;" :: "r"(s), "l"(g));
}
__device__ __forceinline__ void cp_commit() {
    asm volatile("cp.async.commit_group;" ::: "memory");
}
template<int N>
__device__ __forceinline__ void cp_wait() {
    asm volatile("cp.async.wait_group %0;" :: "n"(N) : "memory");
}

// m16n8k16 fp16 MMA, C(f32) += A*B
__device__ __forceinline__ void mma16(float* c, const uint32_t* a, const uint32_t* b) {
    asm volatile(
        "mma.sync.aligned.m16n8k16.row.col.f32.f16.f16.f32 "
        "{%0,%1,%2,%3}, {%4,%5,%6,%7}, {%8,%9}, {%0,%1,%2,%3};"
        : "+f"(c[0]), "+f"(c[1]), "+f"(c[2]), "+f"(c[3])
        : "r"(a[0]), "r"(a[1]), "r"(a[2]), "r"(a[3]), "r"(b[0]), "r"(b[1]));
}

__device__ __forceinline__ uint32_t hmul2u(uint32_t x, uint32_t s) {
    __half2 a = *reinterpret_cast<__half2*>(&x);
    __half2 b = *reinterpret_cast<__half2*>(&s);
    __half2 r = __hmul2(a, b);
    return *reinterpret_cast<uint32_t*>(&r);
}

// ---------------- batched weight transpose: WT[n, p16(k)] = half(W[k,n]) ---------
struct TP8 { const float* src[8]; __half* dst[8]; };

__global__ __launch_bounds__(256) void transpose8_kernel(TP8 p, int K, int N)
{
    __shared__ float t[32][33];
    const float* W = p.src[blockIdx.z];
    __half* WT = p.dst[blockIdx.z];
    int kb = blockIdx.y * 32, nb = blockIdx.x * 32;
    int tx = threadIdx.x & 31, ty4 = (threadIdx.x >> 5) * 4;
    #pragma unroll
    for (int r = 0; r < 4; r++)
        t[ty4 + r][tx] = W[(size_t)(kb + ty4 + r) * N + nb + tx];
    __syncthreads();
    int txp = p16(tx);
    #pragma unroll
    for (int r = 0; r < 4; r++)
        WT[(size_t)(nb + ty4 + r) * K + kb + txp] = __float2half_rn(t[tx][ty4 + r]);
}

__global__ __launch_bounds__(256) void transpose_kernel(
    const float* __restrict__ W, __half* __restrict__ WT, int K, int N)
{
    __shared__ float t[32][33];
    int kb = blockIdx.y * 32, nb = blockIdx.x * 32;
    int tx = threadIdx.x & 31, ty4 = (threadIdx.x >> 5) * 4;
    #pragma unroll
    for (int r = 0; r < 4; r++)
        t[ty4 + r][tx] = W[(size_t)(kb + ty4 + r) * N + nb + tx];
    __syncthreads();
    int txp = p16(tx);
    #pragma unroll
    for (int r = 0; r < 4; r++)
        WT[(size_t)(nb + ty4 + r) * K + kb + txp] = __float2half_rn(t[tx][ty4 + r]);
}

// ---------------- LayerNorm: warp-per-row, no barriers -> half k16-perm ----------
__global__ __launch_bounds__(256) void ln_kernel(
    const float* __restrict__ x, const float* __restrict__ g,
    const float* __restrict__ b, __half* __restrict__ out)
{
    int w = threadIdx.x >> 5, lane = threadIdx.x & 31;
    int row = blockIdx.x * 8 + w;
    const float4* xr = reinterpret_cast<const float4*>(x + (size_t)row * D_);

    float4 v[8];
    float s = 0.f, ss = 0.f;
    #pragma unroll
    for (int j = 0; j < 8; j++) {
        v[j] = xr[lane + 32 * j];
        s  += v[j].x + v[j].y + v[j].z + v[j].w;
        ss += v[j].x*v[j].x + v[j].y*v[j].y + v[j].z*v[j].z + v[j].w*v[j].w;
    }
    #pragma unroll
    for (int o = 16; o; o >>= 1) {
        s  += __shfl_xor_sync(0xffffffffu, s,  o);
        ss += __shfl_xor_sync(0xffffffffu, ss, o);
    }
    float mean = s * (1.0f / D_);
    float var  = ss * (1.0f / D_) - mean * mean;
    float rstd = rsqrtf(var + 1e-5f);

    const float4* gv = reinterpret_cast<const float4*>(g);
    const float4* bv = reinterpret_cast<const float4*>(b);
    __half* orow = out + (size_t)row * D_;
    #pragma unroll
    for (int j = 0; j < 8; j++) {
        int idx = lane + 32 * j;
        float4 g4 = gv[idx], b4 = bv[idx];
        float o0 = (v[j].x - mean) * rstd * g4.x + b4.x;
        float o1 = (v[j].y - mean) * rstd * g4.y + b4.y;
        float o2 = (v[j].z - mean) * rstd * g4.z + b4.z;
        float o3 = (v[j].w - mean) * rstd * g4.w + b4.w;
        int cbase = idx * 4;
        int pos0 = p16(cbase);
        *reinterpret_cast<__half2*>(orow + pos0)     = __floats2half2_rn(o0, o1);
        *reinterpret_cast<__half2*>(orow + pos0 + 4) = __floats2half2_rn(o2, o3);
    }
}

// ---------------- fp16 mma.sync GEMM: C = A[MxK] @ WT[NxK]^T ---------------------
// Block tile MT x 128 (MT = 128 or 256), NT = MT threads, warp tile 64x64,
// BK=32 halves, 3-stage cp.async, LDS.64 fragment loads, stride 48 halves.
// MODE 0: fp32 out (+resid); MODE 1: half k16-perm out; MODE 2: QKV split.
#define SSTR 48
#define GEMM_SMEM_128 (3 * (128 + 128) * SSTR * 2)   // 73728
#define GEMM_SMEM_256 (3 * (256 + 128) * SSTR * 2)   // 110592

template<bool GELU, int MODE, int MT>
__global__ __launch_bounds__(MT) void gemm_mma(
    const __half* __restrict__ A, const __half* __restrict__ WT,
    const float* __restrict__ resid, void* __restrict__ Cout,
    __half* __restrict__ vt_out, int vcol0, int vbatch,
    int M, int N, int K)
{
    constexpr int NT = MT;               // threads = MT (128 -> 4 warps, 256 -> 8)
    constexpr int ASTAGE = MT * SSTR;
    constexpr int BSTAGE = 128 * SSTR;
    extern __shared__ __half smh[];
    __half* As = smh;                    // [3][MT][SSTR]
    __half* Bs = smh + 3 * ASTAGE;       // [3][128][SSTR]

    int tid = threadIdx.x;
    int wid = tid >> 5, lane = tid & 31;
    int warpM = wid >> 1, warpN = wid & 1;
    int grp = lane >> 2, tig = lane & 3;

    int n0 = blockIdx.x * 128, m0 = blockIdx.y * MT;
    const __half* Ab = A  + (size_t)m0 * K;
    const __half* Bb = WT + (size_t)n0 * K;

    float acc[4][8][4];
    #pragma unroll
    for (int i = 0; i < 4; i++)
        #pragma unroll
        for (int j = 0; j < 8; j++)
            #pragma unroll
            for (int q = 0; q < 4; q++) acc[i][j][q] = 0.f;

    int nk = K >> 5;

    auto load_stage = [&](int st, int kt) {
        int k0 = kt << 5;
        __half* Ast = As + st * ASTAGE;
        __half* Bst = Bs + st * BSTAGE;
        #pragma unroll
        for (int i = 0; i < (MT * 4) / NT; i++) {       // 4
            int idx = tid + i * NT;
            int m = idx >> 2, kc = (idx & 3) * 8;
            cp16(smem_u32(Ast + m * SSTR + kc), Ab + (size_t)m * K + k0 + kc);
        }
        #pragma unroll
        for (int i = 0; i < 512 / NT; i++) {            // 4 or 2
            int idx = tid + i * NT;
            int m = idx >> 2, kc = (idx & 3) * 8;
            cp16(smem_u32(Bst + m * SSTR + kc), Bb + (size_t)m * K + k0 + kc);
        }
        cp_commit();
    };

    load_stage(0, 0);
    if (nk > 1) load_stage(1, 1);

    for (int kt = 0; kt < nk; kt++) {
        int buf = kt % 3;
        if (kt + 1 < nk) cp_wait<1>(); else cp_wait<0>();
        __syncthreads();
        if (kt + 2 < nk) load_stage((kt + 2) % 3, kt + 2);

        __half* Abuf = As + buf * ASTAGE;
        __half* Bbuf = Bs + buf * BSTAGE;

        #pragma unroll
        for (int ks = 0; ks < 2; ks++) {
            int kof = ks * 16 + 4 * tig;
            uint32_t af[4][4], bf[8][2];
            #pragma unroll
            for (int mt = 0; mt < 4; mt++) {
                int rA = warpM * 64 + mt * 16 + grp;
                uint2 lo = *reinterpret_cast<const uint2*>(Abuf + rA * SSTR + kof);
                uint2 hi = *reinterpret_cast<const uint2*>(Abuf + (rA + 8) * SSTR + kof);
                af[mt][0] = lo.x; af[mt][1] = hi.x;
                af[mt][2] = lo.y; af[mt][3] = hi.y;
            }
            #pragma unroll
            for (int nt = 0; nt < 8; nt++) {
                int rB = warpN * 64 + nt * 8 + grp;
                uint2 bb = *reinterpret_cast<const uint2*>(Bbuf + rB * SSTR + kof);
                bf[nt][0] = bb.x; bf[nt][1] = bb.y;
            }
            #pragma unroll
            for (int mt = 0; mt < 4; mt++)
                #pragma unroll
                for (int nt = 0; nt < 8; nt++)
                    mma16(acc[mt][nt], af[mt], bf[nt]);
        }
    }

    bool vt_region = (MODE == 2) && (n0 >= vcol0);

    #pragma unroll
    for (int mt = 0; mt < 4; mt++) {
        int row = m0 + warpM * 64 + mt * 16 + grp;
        #pragma unroll
        for (int nt = 0; nt < 8; nt++) {
            int col = n0 + warpN * 64 + nt * 8 + 2 * tig;
            #pragma unroll
            for (int half_ = 0; half_ < 2; half_++) {
                int r = row + half_ * 8;
                float v0 = acc[mt][nt][half_ * 2 + 0];
                float v1 = acc[mt][nt][half_ * 2 + 1];
                if (GELU) {
                    v0 = 0.5f * v0 * (1.0f + erff(v0 * 0.70710678118654752f));
                    v1 = 0.5f * v1 * (1.0f + erff(v1 * 0.70710678118654752f));
                }
                if (MODE == 0) {
                    if (resid) {
                        float2 rv = *reinterpret_cast<const float2*>(resid + (size_t)r * N + col);
                        v0 += rv.x; v1 += rv.y;
                    }
                    float* Cf = (float*)Cout;
                    float2 ov = {v0, v1};
                    *reinterpret_cast<float2*>(Cf + (size_t)r * N + col) = ov;
                } else if (MODE == 1 || !vt_region) {
                    int ldo = (MODE == 2) ? vcol0 : N;
                    __half* C16 = (__half*)Cout;
                    *reinterpret_cast<__half2*>(C16 + (size_t)r * ldo + p16(col)) =
                        __floats2half2_rn(v0, v1);
                } else {
                    int dim = col - vcol0;
                    int batch = r / vbatch;
                    int t = r - batch * vbatch;
                    size_t base = ((size_t)batch * (N - vcol0) + dim) * vbatch + t;
                    vt_out[base]          = __float2half_rn(v0);
                    vt_out[base + vbatch] = __float2half_rn(v1);
                }
            }
        }
    }
}

// ---------------- fp16 tensor-core flash attention (online softmax) --------------
// Qh/Kh: half, k16-permuted dims, row strides qld/kld.
// Vt: half V^T  [batch][dim][key], key stride = kv_tokens_per_batch.
// O: half, k16-permuted (GEMM A operand), stride D_.
// CAUSAL: qt reversed (longest CTAs launch first -> LPT schedule).
#define KSH 80
#define VSH 72
#define PSH 80
#define ATTH_HALVES (2 * (64 * KSH + 64 * VSH) + 4 * 16 * PSH)
#define ATTH_BYTES  (ATTH_HALVES * 2)

template<bool CAUSAL>
__global__ __launch_bounds__(128) void attn_h(
    const __half* __restrict__ Qh, const __half* __restrict__ Kh,
    const __half* __restrict__ Vt, __half* __restrict__ O,
    int klen, int qtpb, int kvtpb, int qld, int kld)
{
    extern __shared__ __half smh[];
    int tid = threadIdx.x, w = tid >> 5, lane = tid & 31;
    int grp = lane >> 2, tig = lane & 3;
    int qt = CAUSAL ? (gridDim.x - 1 - blockIdx.x) : blockIdx.x;
    int h = blockIdx.y, b = blockIdx.z;
    int qbase = b * qtpb + qt * 64;

    const int KV_BUF = 64 * KSH + 64 * VSH;
    __half* Ks0 = smh;
    __half* Vs0 = smh + 64 * KSH;
    __half* Ks1 = smh + KV_BUF;
    __half* Vs1 = smh + KV_BUF + 64 * KSH;
    __half* Ps  = smh + 2 * KV_BUF + w * (16 * PSH);

    // ---- stage Q (half, permuted) into Ks0, build scaled A-fragments ----
    for (int i = tid; i < 64 * 8; i += 128) {
        int r = i >> 3, c = (i & 7) * 8;
        *reinterpret_cast<uint4*>(&Ks0[r * KSH + c]) =
            *reinterpret_cast<const uint4*>(&Qh[(size_t)(qbase + r) * qld + h * HD_ + c]);
    }
    __syncthreads();
    uint32_t aq[4][4];
    {
        __half2 sch = __half2half2(__float2half(0.125f));   // exact
        uint32_t sc = *reinterpret_cast<uint32_t*>(&sch);
        int r0 = w * 16 + grp;
        #pragma unroll
        for (int ko = 0; ko < 4; ko++) {
            int base = 16 * ko + 4 * tig;
            uint2 lo = *reinterpret_cast<const uint2*>(&Ks0[r0 * KSH + base]);
            uint2 hi = *reinterpret_cast<const uint2*>(&Ks0[(r0 + 8) * KSH + base]);
            aq[ko][0] = hmul2u(lo.x, sc); aq[ko][1] = hmul2u(hi.x, sc);
            aq[ko][2] = hmul2u(lo.y, sc); aq[ko][3] = hmul2u(hi.y, sc);
        }
    }
    __syncthreads();

    float o[8][4];
    #pragma unroll
    for (int i = 0; i < 8; i++)
        #pragma unroll
        for (int j = 0; j < 4; j++) o[i][j] = 0.f;
    float m0 = -1e30f, m1 = -1e30f, l0 = 0.f, l1 = 0.f;

    int ktiles = klen >> 6;
    if (CAUSAL && qt + 1 < ktiles) ktiles = qt + 1;

    auto load_kv = [&](__half* Ks, __half* Vs, int kt) {
        int kb = kt * 64;
        for (int i = tid; i < 512; i += 128) {
            int r = i >> 3, c = (i & 7) * 8;
            cp16(smem_u32(&Ks[r * KSH + c]),
                 Kh + (size_t)(b * kvtpb + kb + r) * kld + h * HD_ + c);
            cp16(smem_u32(&Vs[r * VSH + c]),
                 Vt + ((size_t)(b * D_ + h * HD_ + r)) * kvtpb + kb + c);
        }
        cp_commit();
    };

    load_kv(Ks0, Vs0, 0);

    for (int kt = 0; kt < ktiles; kt++) {
        int buf = kt & 1;
        __half* Ks = buf ? Ks1 : Ks0;
        __half* Vs = buf ? Vs1 : Vs0;
        if (kt + 1 < ktiles) {
            load_kv(buf ? Ks0 : Ks1, buf ? Vs0 : Vs1, kt + 1);
            cp_wait<1>();
        } else {
            cp_wait<0>();
        }
        __syncthreads();

        // ---- S = Q @ K^T (fp16 k16) ----
        float s[8][4];
        #pragma unroll
        for (int nt = 0; nt < 8; nt++)
            #pragma unroll
            for (int j = 0; j < 4; j++) s[nt][j] = 0.f;

        #pragma unroll
        for (int ko = 0; ko < 4; ko++) {
            int kof = 16 * ko + 4 * tig;
            #pragma unroll
            for (int nt = 0; nt < 8; nt++) {
                int key = nt * 8 + grp;
                uint2 bb = *reinterpret_cast<const uint2*>(&Ks[key * KSH + kof]);
                uint32_t bk[2] = {bb.x, bb.y};
                mma16(s[nt], aq[ko], bk);
            }
        }

        if (CAUSAL && kt == qt) {
            int r0 = qt * 64 + w * 16 + grp;
            #pragma unroll
            for (int nt = 0; nt < 8; nt++) {
                int c = kt * 64 + nt * 8 + 2 * tig;
                if (c     > r0)     s[nt][0] = -1e30f;
                if (c + 1 > r0)     s[nt][1] = -1e30f;
                if (c     > r0 + 8) s[nt][2] = -1e30f;
                if (c + 1 > r0 + 8) s[nt][3] = -1e30f;
            }
        }

        // ---- online softmax ----
        float t0 = -1e30f, t1 = -1e30f;
        #pragma unroll
        for (int nt = 0; nt < 8; nt++) {
            t0 = fmaxf(t0, fmaxf(s[nt][0], s[nt][1]));
            t1 = fmaxf(t1, fmaxf(s[nt][2], s[nt][3]));
        }
        t0 = fmaxf(t0, __shfl_xor_sync(0xffffffffu, t0, 1));
        t0 = fmaxf(t0, __shfl_xor_sync(0xffffffffu, t0, 2));
        t1 = fmaxf(t1, __shfl_xor_sync(0xffffffffu, t1, 1));
        t1 = fmaxf(t1, __shfl_xor_sync(0xffffffffu, t1, 2));
        float nm0 = fmaxf(m0, t0), nm1 = fmaxf(m1, t1);
        float c0 = __expf(m0 - nm0), c1 = __expf(m1 - nm1);
        float ts0 = 0.f, ts1 = 0.f;
        #pragma unroll
        for (int nt = 0; nt < 8; nt++) {
            s[nt][0] = __expf(s[nt][0] - nm0);
            s[nt][1] = __expf(s[nt][1] - nm0);
            s[nt][2] = __expf(s[nt][2] - nm1);
            s[nt][3] = __expf(s[nt][3] - nm1);
            ts0 += s[nt][0] + s[nt][1];
            ts1 += s[nt][2] + s[nt][3];
        }
        ts0 += __shfl_xor_sync(0xffffffffu, ts0, 1);
        ts0 += __shfl_xor_sync(0xffffffffu, ts0, 2);
        ts1 += __shfl_xor_sync(0xffffffffu, ts1, 1);
        ts1 += __shfl_xor_sync(0xffffffffu, ts1, 2);
        l0 = l0 * c0 + ts0;
        l1 = l1 * c1 + ts1;
        m0 = nm0; m1 = nm1;
        #pragma unroll
        for (int nt = 0; nt < 8; nt++) {
            o[nt][0] *= c0; o[nt][1] *= c0;
            o[nt][2] *= c1; o[nt][3] *= c1;
        }

        // ---- P -> half, key-permuted, warp-private smem ----
        #pragma unroll
        for (int nt = 0; nt < 8; nt++) {
            int pos = (nt >> 1) * 16 + 4 * tig + 2 * (nt & 1);
            *reinterpret_cast<__half2*>(&Ps[grp * PSH + pos]) =
                __floats2half2_rn(s[nt][0], s[nt][1]);
            *reinterpret_cast<__half2*>(&Ps[(grp + 8) * PSH + pos]) =
                __floats2half2_rn(s[nt][2], s[nt][3]);
        }
        __syncwarp();

        // ---- O += P @ V (fp16 k16, V^T dim-major smem) ----
        #pragma unroll
        for (int ko = 0; ko < 4; ko++) {
            int kof = 16 * ko + 4 * tig;
            uint2 lo = *reinterpret_cast<const uint2*>(&Ps[grp * PSH + kof]);
            uint2 hi = *reinterpret_cast<const uint2*>(&Ps[(grp + 8) * PSH + kof]);
            uint32_t ap[4] = {lo.x, hi.x, lo.y, hi.y};
            #pragma unroll
            for (int nt2 = 0; nt2 < 8; nt2++) {
                int n = nt2 * 8 + grp;
                uint32_t bv[2];
                bv[0] = *reinterpret_cast<const uint32_t*>(&Vs[n * VSH + 16 * ko + 2 * tig]);
                bv[1] = *reinterpret_cast<const uint32_t*>(&Vs[n * VSH + 16 * ko + 2 * tig + 8]);
                mma16(o[nt2], ap, bv);
            }
        }
        __syncwarp();
        __syncthreads();
    }

    // ---- epilogue: half, k16-permuted ----
    float il0 = 1.0f / l0, il1 = 1.0f / l1;
    int r0 = qbase + w * 16 + grp;
    #pragma unroll
    for (int nt2 = 0; nt2 < 8; nt2++) {
        int col = h * HD_ + nt2 * 8 + 2 * tig;
        int pos = p16(col);
        *reinterpret_cast<__half2*>(O + (size_t)r0 * D_ + pos) =
            __floats2half2_rn(o[nt2][0] * il0, o[nt2][1] * il0);
        *reinterpret_cast<__half2*>(O + (size_t)(r0 + 8) * D_ + pos) =
            __floats2half2_rn(o[nt2][2] * il1, o[nt2][3] * il1);
    }
}

// ---------------- launch ---------------------------------------------------------
extern "C" void kernel_launch(void* const* d_in, const int* in_sizes, int n_in,
                              void* d_out, int out_size)
{
    const float* x         = (const float*)d_in[0];
    const float* neighbors = (const float*)d_in[1];
    const float* sa_ln_g   = (const float*)d_in[2];
    const float* sa_ln_b   = (const float*)d_in[3];
    const float* sa_wq     = (const float*)d_in[4];
    const float* sa_wk     = (const float*)d_in[5];
    const float* sa_wv     = (const float*)d_in[6];
    const float* sa_wo     = (const float*)d_in[7];
    const float* cca_lnq_g = (const float*)d_in[8];
    const float* cca_lnq_b = (const float*)d_in[9];
    const float* cca_lnkv_g= (const float*)d_in[10];
    const float* cca_lnkv_b= (const float*)d_in[11];
    const float* cca_wq    = (const float*)d_in[12];
    const float* cca_wk    = (const float*)d_in[13];
    const float* cca_wv    = (const float*)d_in[14];
    const float* cca_wo    = (const float*)d_in[15];
    const float* ffn_ln_g  = (const float*)d_in[16];
    const float* ffn_ln_b  = (const float*)d_in[17];
    const float* ffn_w1    = (const float*)d_in[18];
    const float* ffn_w2    = (const float*)d_in[19];
    float* out = (float*)d_out;

    __half *h, *kvln, *attn, *ffn, *wt, *qk, *vt, *ccq, *cck, *ccvt;
    float *x1;
    cudaGetSymbolAddress((void**)&h,    g_h);
    cudaGetSymbolAddress((void**)&kvln, g_kvln);
    cudaGetSymbolAddress((void**)&attn, g_attn);
    cudaGetSymbolAddress((void**)&ffn,  g_ffn);
    cudaGetSymbolAddress((void**)&wt,   g_wt);
    cudaGetSymbolAddress((void**)&qk,   g_qk);
    cudaGetSymbolAddress((void**)&vt,   g_vt);
    cudaGetSymbolAddress((void**)&ccq,  g_ccq);
    cudaGetSymbolAddress((void**)&cck,  g_cck);
    cudaGetSymbolAddress((void**)&ccvt, g_ccvt);
    cudaGetSymbolAddress((void**)&x1,   g_x1);

    const size_t MB = 1024 * 1024;
    __half* wt_saqkv = wt + 0 * MB;   // [3072, 1024]
    __half* wt_sao   = wt + 3 * MB;
    __half* wt_ccq   = wt + 4 * MB;
    __half* wt_cckv  = wt + 5 * MB;   // [2048, 1024]
    __half* wt_cco   = wt + 7 * MB;
    __half* wt_f1    = wt + 8 * MB;   // [DFF, D]
    __half* wt_f2    = wt + 12 * MB;  // [D, DFF]

    cudaFuncSetAttribute(attn_h<true >, cudaFuncAttributeMaxDynamicSharedMemorySize, ATTH_BYTES);
    cudaFuncSetAttribute(attn_h<false>, cudaFuncAttributeMaxDynamicSharedMemorySize, ATTH_BYTES);
    cudaFuncSetAttribute((const void*)&gemm_mma<false,0,128>,
                         cudaFuncAttributeMaxDynamicSharedMemorySize, GEMM_SMEM_128);
    cudaFuncSetAttribute((const void*)&gemm_mma<false,1,128>,
                         cudaFuncAttributeMaxDynamicSharedMemorySize, GEMM_SMEM_128);
    cudaFuncSetAttribute((const void*)&gemm_mma<false,2,256>,
                         cudaFuncAttributeMaxDynamicSharedMemorySize, GEMM_SMEM_256);
    cudaFuncSetAttribute((const void*)&gemm_mma<true ,1,256>,
                         cudaFuncAttributeMaxDynamicSharedMemorySize, GEMM_SMEM_256);

    dim3 blk256(256), blk128(128);

    // ---- batched weight transposes (fp32 -> half, k16-permuted) ----
    TP8 tp;
    tp.src[0] = sa_wq;  tp.dst[0] = wt_saqkv + 0 * MB;
    tp.src[1] = sa_wk;  tp.dst[1] = wt_saqkv + 1 * MB;
    tp.src[2] = sa_wv;  tp.dst[2] = wt_saqkv + 2 * MB;
    tp.src[3] = sa_wo;  tp.dst[3] = wt_sao;
    tp.src[4] = cca_wq; tp.dst[4] = wt_ccq;
    tp.src[5] = cca_wk; tp.dst[5] = wt_cckv + 0 * MB;
    tp.src[6] = cca_wv; tp.dst[6] = wt_cckv + 1 * MB;
    tp.src[7] = cca_wo; tp.dst[7] = wt_cco;
    transpose8_kernel<<<dim3(D_ / 32, D_ / 32, 8), blk256>>>(tp, D_, D_);
    transpose_kernel<<<dim3(DFF_ / 32, D_ / 32), blk256>>>(ffn_w1, wt_f1, D_, DFF_);
    transpose_kernel<<<dim3(D_ / 32, DFF_ / 32), blk256>>>(ffn_w2, wt_f2, DFF_, D_);

    dim3 gProj(D_ / 128, TOK_ / 128);            // (8, 32)   MT=128
    dim3 gQKV(3 * D_ / 128, TOK_ / 256);         // (24, 16)  MT=256
    dim3 gKV2(2 * D_ / 128, KVTOK_ / 256);       // (16, 64)  MT=256
    dim3 gFFN1(DFF_ / 128, TOK_ / 256);          // (32, 16)  MT=256

    // ---- self-attention ----
    ln_kernel<<<TOK_ / 8, blk256>>>(x, sa_ln_g, sa_ln_b, h);
    gemm_mma<false,2,256><<<gQKV, blk256, GEMM_SMEM_256>>>(
        h, wt_saqkv, nullptr, qk, vt, 2 * D_, T_, TOK_, 3 * D_, D_);
    attn_h<true><<<dim3(T_ / 64, H_, B_), blk128, ATTH_BYTES>>>(
        qk, qk + D_, vt, attn, T_, T_, T_, 2 * D_, 2 * D_);
    gemm_mma<false,0,128><<<gProj, blk128, GEMM_SMEM_128>>>(
        attn, wt_sao, x, x1, nullptr, 0, 0, TOK_, D_, D_);

    // ---- chunked cross-attention (T == NC*chunk; reshapes are views) ----
    ln_kernel<<<TOK_ / 8,  blk256>>>(x1, cca_lnq_g, cca_lnq_b, h);
    ln_kernel<<<KVTOK_ / 8, blk256>>>(neighbors, cca_lnkv_g, cca_lnkv_b, kvln);
    gemm_mma<false,1,128><<<gProj, blk128, GEMM_SMEM_128>>>(
        h, wt_ccq, nullptr, ccq, nullptr, 0, 0, TOK_, D_, D_);
    gemm_mma<false,2,256><<<gKV2, blk256, GEMM_SMEM_256>>>(
        kvln, wt_cckv, nullptr, cck, ccvt, D_, KV_, KVTOK_, 2 * D_, D_);
    attn_h<false><<<dim3(1, H_, NCH_), blk128, ATTH_BYTES>>>(
        ccq, cck, ccvt, attn, KV_, CH_, KV_, D_, D_);
    gemm_mma<false,0,128><<<gProj, blk128, GEMM_SMEM_128>>>(
        attn, wt_cco, x1, out, nullptr, 0, 0, TOK_, D_, D_);

    // ---- FFN ----
    ln_kernel<<<TOK_ / 8, blk256>>>(out, ffn_ln_g, ffn_ln_b, h);
    gemm_mma<true ,1,256><<<gFFN1, blk256, GEMM_SMEM_256>>>(
        h, wt_f1, nullptr, ffn, nullptr, 0, 0, TOK_, DFF_, D_);
    gemm_mma<false,0,128><<<gProj, blk128, GEMM_SMEM_128>>>(
        ffn, wt_f2, out, out, nullptr, 0, 0, TOK_, D_, DFF_);
}

// round 13
// speedup vs baseline: 1.0693x; 1.0693x over previous
#include <cuda_runtime.h>
#include <cuda_fp16.h>
#include <math.h>
#include <cstdint>

// Problem constants (fixed by setup_inputs)
#define B_     2
#define T_     2048
#define D_     1024
#define H_     16
#define HD_    64
#define TOK_   4096      // B*T
#define NCH_   64        // B*NC chunks
#define CH_    64        // chunk_size
#define KV_    256       // K*NL
#define KVTOK_ 16384     // NCH_*KV_
#define DFF_   4096

// ---------------- scratch (static device globals; no allocation) ----------------
__device__ __half g_h   [TOK_  * D_];      // LN out (GEMM A, half k16-perm)
__device__ __half g_kvln[KVTOK_* D_];
__device__ __half g_attn[TOK_  * D_];      // attention out (GEMM A)
__device__ __half g_ffn [TOK_  * DFF_];    // GELU out (GEMM A)
__device__ __half g_wt  [16u * 1024u * 1024u];  // transposed weights (GEMM B)
__device__ __half g_qk  [TOK_  * 2 * D_];  // SA q|k (half, k16-perm)
__device__ __half g_vt  [TOK_  * D_];      // SA V^T: [b][dim][token]
__device__ __half g_ccq [TOK_  * D_];      // CCA q (half perm)
__device__ __half g_cck [KVTOK_* D_];      // CCA k (half perm)
__device__ __half g_ccvt[KVTOK_* D_];      // CCA V^T: [chunk][dim][key]
__device__ float  g_x1  [TOK_  * D_];

// ---------------- helpers ---------------------------------------------------------
__device__ __forceinline__ uint32_t smem_u32(const void* p) {
    uint32_t a;
    asm("{ .reg .u64 t; cvta.to.shared.u64 t, %1; cvt.u32.u64 %0, t; }" : "=r"(a) : "l"(p));
    return a;
}

// k16 permutation: original col c -> packed pos (pairs (2t,2t+1),(2t+8,2t+9) adjacent)
__device__ __forceinline__ int p16(int c) {
    return (c & ~15) + 4 * ((c & 7) >> 1) + 2 * ((c >> 3) & 1) + (c & 1);
}

__device__ __forceinline__ void cp16(uint32_t s, const void* g) {
    asm volatile("cp.async.cg.shared.global [%0], [%1], 16;" :: "r"(s), "l"(g));
}
__device__ __forceinline__ void cp_commit() {
    asm volatile("cp.async.commit_group;" ::: "memory");
}
template<int N>
__device__ __forceinline__ void cp_wait() {
    asm volatile("cp.async.wait_group %0;" :: "n"(N) : "memory");
}

// m16n8k16 fp16 MMA, C(f32) += A*B
__device__ __forceinline__ void mma16(float* c, const uint32_t* a, const uint32_t* b) {
    asm volatile(
        "mma.sync.aligned.m16n8k16.row.col.f32.f16.f16.f32 "
        "{%0,%1,%2,%3}, {%4,%5,%6,%7}, {%8,%9}, {%0,%1,%2,%3};"
        : "+f"(c[0]), "+f"(c[1]), "+f"(c[2]), "+f"(c[3])
        : "r"(a[0]), "r"(a[1]), "r"(a[2]), "r"(a[3]), "r"(b[0]), "r"(b[1]));
}

__device__ __forceinline__ uint32_t hmul2u(uint32_t x, uint32_t s) {
    __half2 a = *reinterpret_cast<__half2*>(&x);
    __half2 b = *reinterpret_cast<__half2*>(&s);
    __half2 r = __hmul2(a, b);
    return *reinterpret_cast<uint32_t*>(&r);
}

// ---------------- batched weight transpose: WT[n, p16(k)] = half(W[k,n]) ---------
struct TP8 { const float* src[8]; __half* dst[8]; };

__global__ __launch_bounds__(256) void transpose8_kernel(TP8 p, int K, int N)
{
    __shared__ float t[32][33];
    const float* W = p.src[blockIdx.z];
    __half* WT = p.dst[blockIdx.z];
    int kb = blockIdx.y * 32, nb = blockIdx.x * 32;
    int tx = threadIdx.x & 31, ty4 = (threadIdx.x >> 5) * 4;
    #pragma unroll
    for (int r = 0; r < 4; r++)
        t[ty4 + r][tx] = W[(size_t)(kb + ty4 + r) * N + nb + tx];
    __syncthreads();
    int txp = p16(tx);
    #pragma unroll
    for (int r = 0; r < 4; r++)
        WT[(size_t)(nb + ty4 + r) * K + kb + txp] = __float2half_rn(t[tx][ty4 + r]);
}

__global__ __launch_bounds__(256) void transpose_kernel(
    const float* __restrict__ W, __half* __restrict__ WT, int K, int N)
{
    __shared__ float t[32][33];
    int kb = blockIdx.y * 32, nb = blockIdx.x * 32;
    int tx = threadIdx.x & 31, ty4 = (threadIdx.x >> 5) * 4;
    #pragma unroll
    for (int r = 0; r < 4; r++)
        t[ty4 + r][tx] = W[(size_t)(kb + ty4 + r) * N + nb + tx];
    __syncthreads();
    int txp = p16(tx);
    #pragma unroll
    for (int r = 0; r < 4; r++)
        WT[(size_t)(nb + ty4 + r) * K + kb + txp] = __float2half_rn(t[tx][ty4 + r]);
}

// ---------------- LayerNorm: warp-per-row, no barriers -> half k16-perm ----------
__global__ __launch_bounds__(256) void ln_kernel(
    const float* __restrict__ x, const float* __restrict__ g,
    const float* __restrict__ b, __half* __restrict__ out)
{
    int w = threadIdx.x >> 5, lane = threadIdx.x & 31;
    int row = blockIdx.x * 8 + w;
    const float4* xr = reinterpret_cast<const float4*>(x + (size_t)row * D_);

    float4 v[8];
    float s = 0.f, ss = 0.f;
    #pragma unroll
    for (int j = 0; j < 8; j++) {
        v[j] = xr[lane + 32 * j];
        s  += v[j].x + v[j].y + v[j].z + v[j].w;
        ss += v[j].x*v[j].x + v[j].y*v[j].y + v[j].z*v[j].z + v[j].w*v[j].w;
    }
    #pragma unroll
    for (int o = 16; o; o >>= 1) {
        s  += __shfl_xor_sync(0xffffffffu, s,  o);
        ss += __shfl_xor_sync(0xffffffffu, ss, o);
    }
    float mean = s * (1.0f / D_);
    float var  = ss * (1.0f / D_) - mean * mean;
    float rstd = rsqrtf(var + 1e-5f);

    const float4* gv = reinterpret_cast<const float4*>(g);
    const float4* bv = reinterpret_cast<const float4*>(b);
    __half* orow = out + (size_t)row * D_;
    #pragma unroll
    for (int j = 0; j < 8; j++) {
        int idx = lane + 32 * j;
        float4 g4 = gv[idx], b4 = bv[idx];
        float o0 = (v[j].x - mean) * rstd * g4.x + b4.x;
        float o1 = (v[j].y - mean) * rstd * g4.y + b4.y;
        float o2 = (v[j].z - mean) * rstd * g4.z + b4.z;
        float o3 = (v[j].w - mean) * rstd * g4.w + b4.w;
        int cbase = idx * 4;
        int pos0 = p16(cbase);
        *reinterpret_cast<__half2*>(orow + pos0)     = __floats2half2_rn(o0, o1);
        *reinterpret_cast<__half2*>(orow + pos0 + 4) = __floats2half2_rn(o2, o3);
    }
}

// ---------------- fp16 mma.sync GEMM: C = A[MxK] @ WT[NxK]^T ---------------------
// 128x128 block tile, 128 threads (4 warps, 2x2), warp tile 64x64, BK=32 halves,
// 3-stage cp.async, LDS.64 fragment loads, stride 48 halves (conflict-free).
// MODE 0: fp32 out (+resid); MODE 1: half k16-perm out; MODE 2: QKV split
//   (cols < vcol0 -> half perm, stride vcol0; cols >= vcol0 -> V^T half
//    vt[batch][dim][t], batch = r / vbatch).
#define SSTR 48
#define HSTAGE (128 * SSTR)
#define GEMM_SMEM (3 * 2 * HSTAGE * 2)      // 73728 bytes

template<bool GELU, int MODE>
__global__ __launch_bounds__(128) void gemm_mma(
    const __half* __restrict__ A, const __half* __restrict__ WT,
    const float* __restrict__ resid, void* __restrict__ Cout,
    __half* __restrict__ vt_out, int vcol0, int vbatch,
    int M, int N, int K)
{
    extern __shared__ __half smh[];
    __half* As = smh;                 // [3][128][SSTR]
    __half* Bs = smh + 3 * HSTAGE;

    int tid = threadIdx.x;
    int wid = tid >> 5, lane = tid & 31;
    int warpM = wid >> 1, warpN = wid & 1;
    int grp = lane >> 2, tig = lane & 3;

    int n0 = blockIdx.x * 128, m0 = blockIdx.y * 128;
    const __half* Ab = A  + (size_t)m0 * K;
    const __half* Bb = WT + (size_t)n0 * K;

    float acc[4][8][4];
    #pragma unroll
    for (int i = 0; i < 4; i++)
        #pragma unroll
        for (int j = 0; j < 8; j++)
            #pragma unroll
            for (int q = 0; q < 4; q++) acc[i][j][q] = 0.f;

    int nk = K >> 5;

    auto load_stage = [&](int st, int kt) {
        int k0 = kt << 5;
        __half* Ast = As + st * HSTAGE;
        __half* Bst = Bs + st * HSTAGE;
        #pragma unroll
        for (int i = 0; i < 4; i++) {
            int idx = tid + i * 128;
            int m = idx >> 2, kc = (idx & 3) * 8;
            cp16(smem_u32(Ast + m * SSTR + kc), Ab + (size_t)m * K + k0 + kc);
            cp16(smem_u32(Bst + m * SSTR + kc), Bb + (size_t)m * K + k0 + kc);
        }
        cp_commit();
    };

    load_stage(0, 0);
    if (nk > 1) load_stage(1, 1);

    for (int kt = 0; kt < nk; kt++) {
        int buf = kt % 3;
        if (kt + 1 < nk) cp_wait<1>(); else cp_wait<0>();
        __syncthreads();
        if (kt + 2 < nk) load_stage((kt + 2) % 3, kt + 2);

        __half* Abuf = As + buf * HSTAGE;
        __half* Bbuf = Bs + buf * HSTAGE;

        #pragma unroll
        for (int ks = 0; ks < 2; ks++) {
            int kof = ks * 16 + 4 * tig;
            uint32_t af[4][4], bf[8][2];
            #pragma unroll
            for (int mt = 0; mt < 4; mt++) {
                int rA = warpM * 64 + mt * 16 + grp;
                uint2 lo = *reinterpret_cast<const uint2*>(Abuf + rA * SSTR + kof);
                uint2 hi = *reinterpret_cast<const uint2*>(Abuf + (rA + 8) * SSTR + kof);
                af[mt][0] = lo.x; af[mt][1] = hi.x;
                af[mt][2] = lo.y; af[mt][3] = hi.y;
            }
            #pragma unroll
            for (int nt = 0; nt < 8; nt++) {
                int rB = warpN * 64 + nt * 8 + grp;
                uint2 bb = *reinterpret_cast<const uint2*>(Bbuf + rB * SSTR + kof);
                bf[nt][0] = bb.x; bf[nt][1] = bb.y;
            }
            #pragma unroll
            for (int mt = 0; mt < 4; mt++)
                #pragma unroll
                for (int nt = 0; nt < 8; nt++)
                    mma16(acc[mt][nt], af[mt], bf[nt]);
        }
    }

    bool vt_region = (MODE == 2) && (n0 >= vcol0);

    #pragma unroll
    for (int mt = 0; mt < 4; mt++) {
        int row = m0 + warpM * 64 + mt * 16 + grp;
        #pragma unroll
        for (int nt = 0; nt < 8; nt++) {
            int col = n0 + warpN * 64 + nt * 8 + 2 * tig;
            #pragma unroll
            for (int half_ = 0; half_ < 2; half_++) {
                int r = row + half_ * 8;
                float v0 = acc[mt][nt][half_ * 2 + 0];
                float v1 = acc[mt][nt][half_ * 2 + 1];
                if (GELU) {
                    v0 = 0.5f * v0 * (1.0f + erff(v0 * 0.70710678118654752f));
                    v1 = 0.5f * v1 * (1.0f + erff(v1 * 0.70710678118654752f));
                }
                if (MODE == 0) {
                    if (resid) {
                        float2 rv = *reinterpret_cast<const float2*>(resid + (size_t)r * N + col);
                        v0 += rv.x; v1 += rv.y;
                    }
                    float* Cf = (float*)Cout;
                    float2 ov = {v0, v1};
                    *reinterpret_cast<float2*>(Cf + (size_t)r * N + col) = ov;
                } else if (MODE == 1 || !vt_region) {
                    int ldo = (MODE == 2) ? vcol0 : N;
                    __half* C16 = (__half*)Cout;
                    *reinterpret_cast<__half2*>(C16 + (size_t)r * ldo + p16(col)) =
                        __floats2half2_rn(v0, v1);
                } else {
                    int dim = col - vcol0;
                    int batch = r / vbatch;
                    int t = r - batch * vbatch;
                    size_t base = ((size_t)batch * (N - vcol0) + dim) * vbatch + t;
                    vt_out[base]          = __float2half_rn(v0);
                    vt_out[base + vbatch] = __float2half_rn(v1);
                }
            }
        }
    }
}

// ---------------- fp16 tensor-core flash attention (online softmax) --------------
// Qh/Kh: half, k16-permuted dims, row strides qld/kld.
// Vt: half V^T  [batch][dim][key], key stride = kv_tokens_per_batch.
// O: half, k16-permuted (GEMM A operand), stride D_.
// CAUSAL: qt reversed (longest CTAs launch first -> LPT schedule).
#define KSH 80
#define VSH 72
#define PSH 80
#define ATTH_HALVES (2 * (64 * KSH + 64 * VSH) + 4 * 16 * PSH)
#define ATTH_BYTES  (ATTH_HALVES * 2)

template<bool CAUSAL>
__global__ __launch_bounds__(128) void attn_h(
    const __half* __restrict__ Qh, const __half* __restrict__ Kh,
    const __half* __restrict__ Vt, __half* __restrict__ O,
    int klen, int qtpb, int kvtpb, int qld, int kld)
{
    extern __shared__ __half smh[];
    int tid = threadIdx.x, w = tid >> 5, lane = tid & 31;
    int grp = lane >> 2, tig = lane & 3;
    int qt = CAUSAL ? (gridDim.x - 1 - blockIdx.x) : blockIdx.x;
    int h = blockIdx.y, b = blockIdx.z;
    int qbase = b * qtpb + qt * 64;

    const int KV_BUF = 64 * KSH + 64 * VSH;
    __half* Ks0 = smh;
    __half* Vs0 = smh + 64 * KSH;
    __half* Ks1 = smh + KV_BUF;
    __half* Vs1 = smh + KV_BUF + 64 * KSH;
    __half* Ps  = smh + 2 * KV_BUF + w * (16 * PSH);

    // ---- stage Q (half, permuted) into Ks0, build scaled A-fragments ----
    for (int i = tid; i < 64 * 8; i += 128) {
        int r = i >> 3, c = (i & 7) * 8;
        *reinterpret_cast<uint4*>(&Ks0[r * KSH + c]) =
            *reinterpret_cast<const uint4*>(&Qh[(size_t)(qbase + r) * qld + h * HD_ + c]);
    }
    __syncthreads();
    uint32_t aq[4][4];
    {
        __half2 sch = __half2half2(__float2half(0.125f));   // exact
        uint32_t sc = *reinterpret_cast<uint32_t*>(&sch);
        int r0 = w * 16 + grp;
        #pragma unroll
        for (int ko = 0; ko < 4; ko++) {
            int base = 16 * ko + 4 * tig;
            uint2 lo = *reinterpret_cast<const uint2*>(&Ks0[r0 * KSH + base]);
            uint2 hi = *reinterpret_cast<const uint2*>(&Ks0[(r0 + 8) * KSH + base]);
            aq[ko][0] = hmul2u(lo.x, sc); aq[ko][1] = hmul2u(hi.x, sc);
            aq[ko][2] = hmul2u(lo.y, sc); aq[ko][3] = hmul2u(hi.y, sc);
        }
    }
    __syncthreads();

    float o[8][4];
    #pragma unroll
    for (int i = 0; i < 8; i++)
        #pragma unroll
        for (int j = 0; j < 4; j++) o[i][j] = 0.f;
    float m0 = -1e30f, m1 = -1e30f, l0 = 0.f, l1 = 0.f;

    int ktiles = klen >> 6;
    if (CAUSAL && qt + 1 < ktiles) ktiles = qt + 1;

    auto load_kv = [&](__half* Ks, __half* Vs, int kt) {
        int kb = kt * 64;
        for (int i = tid; i < 512; i += 128) {
            int r = i >> 3, c = (i & 7) * 8;
            cp16(smem_u32(&Ks[r * KSH + c]),
                 Kh + (size_t)(b * kvtpb + kb + r) * kld + h * HD_ + c);
            cp16(smem_u32(&Vs[r * VSH + c]),
                 Vt + ((size_t)(b * D_ + h * HD_ + r)) * kvtpb + kb + c);
        }
        cp_commit();
    };

    load_kv(Ks0, Vs0, 0);

    for (int kt = 0; kt < ktiles; kt++) {
        int buf = kt & 1;
        __half* Ks = buf ? Ks1 : Ks0;
        __half* Vs = buf ? Vs1 : Vs0;
        if (kt + 1 < ktiles) {
            load_kv(buf ? Ks0 : Ks1, buf ? Vs0 : Vs1, kt + 1);
            cp_wait<1>();
        } else {
            cp_wait<0>();
        }
        __syncthreads();

        // ---- S = Q @ K^T (fp16 k16) ----
        float s[8][4];
        #pragma unroll
        for (int nt = 0; nt < 8; nt++)
            #pragma unroll
            for (int j = 0; j < 4; j++) s[nt][j] = 0.f;

        #pragma unroll
        for (int ko = 0; ko < 4; ko++) {
            int kof = 16 * ko + 4 * tig;
            #pragma unroll
            for (int nt = 0; nt < 8; nt++) {
                int key = nt * 8 + grp;
                uint2 bb = *reinterpret_cast<const uint2*>(&Ks[key * KSH + kof]);
                uint32_t bk[2] = {bb.x, bb.y};
                mma16(s[nt], aq[ko], bk);
            }
        }

        if (CAUSAL && kt == qt) {
            int r0 = qt * 64 + w * 16 + grp;
            #pragma unroll
            for (int nt = 0; nt < 8; nt++) {
                int c = kt * 64 + nt * 8 + 2 * tig;
                if (c     > r0)     s[nt][0] = -1e30f;
                if (c + 1 > r0)     s[nt][1] = -1e30f;
                if (c     > r0 + 8) s[nt][2] = -1e30f;
                if (c + 1 > r0 + 8) s[nt][3] = -1e30f;
            }
        }

        // ---- online softmax ----
        float t0 = -1e30f, t1 = -1e30f;
        #pragma unroll
        for (int nt = 0; nt < 8; nt++) {
            t0 = fmaxf(t0, fmaxf(s[nt][0], s[nt][1]));
            t1 = fmaxf(t1, fmaxf(s[nt][2], s[nt][3]));
        }
        t0 = fmaxf(t0, __shfl_xor_sync(0xffffffffu, t0, 1));
        t0 = fmaxf(t0, __shfl_xor_sync(0xffffffffu, t0, 2));
        t1 = fmaxf(t1, __shfl_xor_sync(0xffffffffu, t1, 1));
        t1 = fmaxf(t1, __shfl_xor_sync(0xffffffffu, t1, 2));
        float nm0 = fmaxf(m0, t0), nm1 = fmaxf(m1, t1);
        float c0 = __expf(m0 - nm0), c1 = __expf(m1 - nm1);
        float ts0 = 0.f, ts1 = 0.f;
        #pragma unroll
        for (int nt = 0; nt < 8; nt++) {
            s[nt][0] = __expf(s[nt][0] - nm0);
            s[nt][1] = __expf(s[nt][1] - nm0);
            s[nt][2] = __expf(s[nt][2] - nm1);
            s[nt][3] = __expf(s[nt][3] - nm1);
            ts0 += s[nt][0] + s[nt][1];
            ts1 += s[nt][2] + s[nt][3];
        }
        ts0 += __shfl_xor_sync(0xffffffffu, ts0, 1);
        ts0 += __shfl_xor_sync(0xffffffffu, ts0, 2);
        ts1 += __shfl_xor_sync(0xffffffffu, ts1, 1);
        ts1 += __shfl_xor_sync(0xffffffffu, ts1, 2);
        l0 = l0 * c0 + ts0;
        l1 = l1 * c1 + ts1;
        m0 = nm0; m1 = nm1;
        #pragma unroll
        for (int nt = 0; nt < 8; nt++) {
            o[nt][0] *= c0; o[nt][1] *= c0;
            o[nt][2] *= c1; o[nt][3] *= c1;
        }

        // ---- P -> half, key-permuted, warp-private smem ----
        #pragma unroll
        for (int nt = 0; nt < 8; nt++) {
            int pos = (nt >> 1) * 16 + 4 * tig + 2 * (nt & 1);
            *reinterpret_cast<__half2*>(&Ps[grp * PSH + pos]) =
                __floats2half2_rn(s[nt][0], s[nt][1]);
            *reinterpret_cast<__half2*>(&Ps[(grp + 8) * PSH + pos]) =
                __floats2half2_rn(s[nt][2], s[nt][3]);
        }
        __syncwarp();

        // ---- O += P @ V (fp16 k16, V^T dim-major smem) ----
        #pragma unroll
        for (int ko = 0; ko < 4; ko++) {
            int kof = 16 * ko + 4 * tig;
            uint2 lo = *reinterpret_cast<const uint2*>(&Ps[grp * PSH + kof]);
            uint2 hi = *reinterpret_cast<const uint2*>(&Ps[(grp + 8) * PSH + kof]);
            uint32_t ap[4] = {lo.x, hi.x, lo.y, hi.y};
            #pragma unroll
            for (int nt2 = 0; nt2 < 8; nt2++) {
                int n = nt2 * 8 + grp;
                uint32_t bv[2];
                bv[0] = *reinterpret_cast<const uint32_t*>(&Vs[n * VSH + 16 * ko + 2 * tig]);
                bv[1] = *reinterpret_cast<const uint32_t*>(&Vs[n * VSH + 16 * ko + 2 * tig + 8]);
                mma16(o[nt2], ap, bv);
            }
        }
        __syncwarp();
        __syncthreads();
    }

    // ---- epilogue: half, k16-permuted ----
    float il0 = 1.0f / l0, il1 = 1.0f / l1;
    int r0 = qbase + w * 16 + grp;
    #pragma unroll
    for (int nt2 = 0; nt2 < 8; nt2++) {
        int col = h * HD_ + nt2 * 8 + 2 * tig;
        int pos = p16(col);
        *reinterpret_cast<__half2*>(O + (size_t)r0 * D_ + pos) =
            __floats2half2_rn(o[nt2][0] * il0, o[nt2][1] * il0);
        *reinterpret_cast<__half2*>(O + (size_t)(r0 + 8) * D_ + pos) =
            __floats2half2_rn(o[nt2][2] * il1, o[nt2][3] * il1);
    }
}

// ---------------- launch ---------------------------------------------------------
extern "C" void kernel_launch(void* const* d_in, const int* in_sizes, int n_in,
                              void* d_out, int out_size)
{
    const float* x         = (const float*)d_in[0];
    const float* neighbors = (const float*)d_in[1];
    const float* sa_ln_g   = (const float*)d_in[2];
    const float* sa_ln_b   = (const float*)d_in[3];
    const float* sa_wq     = (const float*)d_in[4];
    const float* sa_wk     = (const float*)d_in[5];
    const float* sa_wv     = (const float*)d_in[6];
    const float* sa_wo     = (const float*)d_in[7];
    const float* cca_lnq_g = (const float*)d_in[8];
    const float* cca_lnq_b = (const float*)d_in[9];
    const float* cca_lnkv_g= (const float*)d_in[10];
    const float* cca_lnkv_b= (const float*)d_in[11];
    const float* cca_wq    = (const float*)d_in[12];
    const float* cca_wk    = (const float*)d_in[13];
    const float* cca_wv    = (const float*)d_in[14];
    const float* cca_wo    = (const float*)d_in[15];
    const float* ffn_ln_g  = (const float*)d_in[16];
    const float* ffn_ln_b  = (const float*)d_in[17];
    const float* ffn_w1    = (const float*)d_in[18];
    const float* ffn_w2    = (const float*)d_in[19];
    float* out = (float*)d_out;

    __half *h, *kvln, *attn, *ffn, *wt, *qk, *vt, *ccq, *cck, *ccvt;
    float *x1;
    cudaGetSymbolAddress((void**)&h,    g_h);
    cudaGetSymbolAddress((void**)&kvln, g_kvln);
    cudaGetSymbolAddress((void**)&attn, g_attn);
    cudaGetSymbolAddress((void**)&ffn,  g_ffn);
    cudaGetSymbolAddress((void**)&wt,   g_wt);
    cudaGetSymbolAddress((void**)&qk,   g_qk);
    cudaGetSymbolAddress((void**)&vt,   g_vt);
    cudaGetSymbolAddress((void**)&ccq,  g_ccq);
    cudaGetSymbolAddress((void**)&cck,  g_cck);
    cudaGetSymbolAddress((void**)&ccvt, g_ccvt);
    cudaGetSymbolAddress((void**)&x1,   g_x1);

    const size_t MB = 1024 * 1024;
    __half* wt_saqkv = wt + 0 * MB;   // [3072, 1024]
    __half* wt_sao   = wt + 3 * MB;
    __half* wt_ccq   = wt + 4 * MB;
    __half* wt_cckv  = wt + 5 * MB;   // [2048, 1024]
    __half* wt_cco   = wt + 7 * MB;
    __half* wt_f1    = wt + 8 * MB;   // [DFF, D]
    __half* wt_f2    = wt + 12 * MB;  // [D, DFF]

    cudaFuncSetAttribute(attn_h<true >, cudaFuncAttributeMaxDynamicSharedMemorySize, ATTH_BYTES);
    cudaFuncSetAttribute(attn_h<false>, cudaFuncAttributeMaxDynamicSharedMemorySize, ATTH_BYTES);
    cudaFuncSetAttribute((const void*)&gemm_mma<false,0>,
                         cudaFuncAttributeMaxDynamicSharedMemorySize, GEMM_SMEM);
    cudaFuncSetAttribute((const void*)&gemm_mma<false,1>,
                         cudaFuncAttributeMaxDynamicSharedMemorySize, GEMM_SMEM);
    cudaFuncSetAttribute((const void*)&gemm_mma<false,2>,
                         cudaFuncAttributeMaxDynamicSharedMemorySize, GEMM_SMEM);
    cudaFuncSetAttribute((const void*)&gemm_mma<true ,1>,
                         cudaFuncAttributeMaxDynamicSharedMemorySize, GEMM_SMEM);

    dim3 blk256(256), blk128(128);

    // ---- batched weight transposes (fp32 -> half, k16-permuted) ----
    TP8 tp;
    tp.src[0] = sa_wq;  tp.dst[0] = wt_saqkv + 0 * MB;
    tp.src[1] = sa_wk;  tp.dst[1] = wt_saqkv + 1 * MB;
    tp.src[2] = sa_wv;  tp.dst[2] = wt_saqkv + 2 * MB;
    tp.src[3] = sa_wo;  tp.dst[3] = wt_sao;
    tp.src[4] = cca_wq; tp.dst[4] = wt_ccq;
    tp.src[5] = cca_wk; tp.dst[5] = wt_cckv + 0 * MB;
    tp.src[6] = cca_wv; tp.dst[6] = wt_cckv + 1 * MB;
    tp.src[7] = cca_wo; tp.dst[7] = wt_cco;
    transpose8_kernel<<<dim3(D_ / 32, D_ / 32, 8), blk256>>>(tp, D_, D_);
    transpose_kernel<<<dim3(DFF_ / 32, D_ / 32), blk256>>>(ffn_w1, wt_f1, D_, DFF_);
    transpose_kernel<<<dim3(D_ / 32, DFF_ / 32), blk256>>>(ffn_w2, wt_f2, DFF_, D_);

    dim3 gProj(D_ / 128, TOK_ / 128);            // (8, 32)
    dim3 gQKV(3 * D_ / 128, TOK_ / 128);         // (24, 32)
    dim3 gKV2(2 * D_ / 128, KVTOK_ / 128);       // (16, 128)
    dim3 gFFN1(DFF_ / 128, TOK_ / 128);          // (32, 32)

    // ---- self-attention ----
    ln_kernel<<<TOK_ / 8, blk256>>>(x, sa_ln_g, sa_ln_b, h);
    gemm_mma<false,2><<<gQKV, blk128, GEMM_SMEM>>>(
        h, wt_saqkv, nullptr, qk, vt, 2 * D_, T_, TOK_, 3 * D_, D_);
    attn_h<true><<<dim3(T_ / 64, H_, B_), blk128, ATTH_BYTES>>>(
        qk, qk + D_, vt, attn, T_, T_, T_, 2 * D_, 2 * D_);
    gemm_mma<false,0><<<gProj, blk128, GEMM_SMEM>>>(
        attn, wt_sao, x, x1, nullptr, 0, 0, TOK_, D_, D_);

    // ---- chunked cross-attention (T == NC*chunk; reshapes are views) ----
    ln_kernel<<<TOK_ / 8,  blk256>>>(x1, cca_lnq_g, cca_lnq_b, h);
    ln_kernel<<<KVTOK_ / 8, blk256>>>(neighbors, cca_lnkv_g, cca_lnkv_b, kvln);
    gemm_mma<false,1><<<gProj, blk128, GEMM_SMEM>>>(
        h, wt_ccq, nullptr, ccq, nullptr, 0, 0, TOK_, D_, D_);
    gemm_mma<false,2><<<gKV2, blk128, GEMM_SMEM>>>(
        kvln, wt_cckv, nullptr, cck, ccvt, D_, KV_, KVTOK_, 2 * D_, D_);
    attn_h<false><<<dim3(1, H_, NCH_), blk128, ATTH_BYTES>>>(
        ccq, cck, ccvt, attn, KV_, CH_, KV_, D_, D_);
    gemm_mma<false,0><<<gProj, blk128, GEMM_SMEM>>>(
        attn, wt_cco, x1, out, nullptr, 0, 0, TOK_, D_, D_);

    // ---- FFN ----
    ln_kernel<<<TOK_ / 8, blk256>>>(out, ffn_ln_g, ffn_ln_b, h);
    gemm_mma<true ,1><<<gFFN1, blk128, GEMM_SMEM>>>(
        h, wt_f1, nullptr, ffn, nullptr, 0, 0, TOK_, DFF_, D_);
    gemm_mma<false,0><<<gProj, blk128, GEMM_SMEM>>>(
        ffn, wt_f2, out, out, nullptr, 0, 0, TOK_, D_, DFF_);
}

// round 14
// speedup vs baseline: 1.0987x; 1.0275x over previous
#include <cuda_runtime.h>
#include <cuda_fp16.h>
#include <math.h>
#include <cstdint>

// Problem constants (fixed by setup_inputs)
#define B_     2
#define T_     2048
#define D_     1024
#define H_     16
#define HD_    64
#define TOK_   4096      // B*T
#define NCH_   64        // B*NC chunks
#define CH_    64        // chunk_size
#define KV_    256       // K*NL
#define KVTOK_ 16384     // NCH_*KV_
#define DFF_   4096

// ---------------- scratch (static device globals; no allocation) ----------------
__device__ __half g_h   [TOK_  * D_];      // LN out (GEMM A, half k16-perm)
__device__ __half g_kvln[KVTOK_* D_];
__device__ __half g_attn[TOK_  * D_];      // attention out (GEMM A)
__device__ __half g_ffn [TOK_  * DFF_];    // GELU out (GEMM A)
__device__ __half g_wt  [16u * 1024u * 1024u];  // transposed weights (GEMM B)
__device__ __half g_qk  [TOK_  * 2 * D_];  // SA q|k (half, k16-perm)
__device__ __half g_vt  [TOK_  * D_];      // SA V^T: [b][dim][token]
__device__ __half g_ccq [TOK_  * D_];      // CCA q (half perm)
__device__ __half g_cck [KVTOK_* D_];      // CCA k (half perm)
__device__ __half g_ccvt[KVTOK_* D_];      // CCA V^T: [chunk][dim][key]
__device__ float  g_x1  [TOK_  * D_];

// ---------------- helpers ---------------------------------------------------------
__device__ __forceinline__ uint32_t smem_u32(const void* p) {
    uint32_t a;
    asm("{ .reg .u64 t; cvta.to.shared.u64 t, %1; cvt.u32.u64 %0, t; }" : "=r"(a) : "l"(p));
    return a;
}

// k16 permutation: original col c -> packed pos (pairs (2t,2t+1),(2t+8,2t+9) adjacent)
__device__ __forceinline__ int p16(int c) {
    return (c & ~15) + 4 * ((c & 7) >> 1) + 2 * ((c >> 3) & 1) + (c & 1);
}

__device__ __forceinline__ void cp16(uint32_t s, const void* g) {
    asm volatile("cp.async.cg.shared.global [%0], [%1], 16;" :: "r"(s), "l"(g));
}
__device__ __forceinline__ void cp_commit() {
    asm volatile("cp.async.commit_group;" ::: "memory");
}
template<int N>
__device__ __forceinline__ void cp_wait() {
    asm volatile("cp.async.wait_group %0;" :: "n"(N) : "memory");
}

// m16n8k16 fp16 MMA, C(f32) += A*B
__device__ __forceinline__ void mma16(float* c, const uint32_t* a, const uint32_t* b) {
    asm volatile(
        "mma.sync.aligned.m16n8k16.row.col.f32.f16.f16.f32 "
        "{%0,%1,%2,%3}, {%4,%5,%6,%7}, {%8,%9}, {%0,%1,%2,%3};"
        : "+f"(c[0]), "+f"(c[1]), "+f"(c[2]), "+f"(c[3])
        : "r"(a[0]), "r"(a[1]), "r"(a[2]), "r"(a[3]), "r"(b[0]), "r"(b[1]));
}

__device__ __forceinline__ uint32_t hmul2u(uint32_t x, uint32_t s) {
    __half2 a = *reinterpret_cast<__half2*>(&x);
    __half2 b = *reinterpret_cast<__half2*>(&s);
    __half2 r = __hmul2(a, b);
    return *reinterpret_cast<uint32_t*>(&r);
}

// ---------------- batched weight transpose: WT[n, p16(k)] = half(W[k,n]) ---------
struct TP8 { const float* src[8]; __half* dst[8]; };

__global__ __launch_bounds__(256) void transpose8_kernel(TP8 p, int K, int N)
{
    __shared__ float t[32][33];
    const float* W = p.src[blockIdx.z];
    __half* WT = p.dst[blockIdx.z];
    int kb = blockIdx.y * 32, nb = blockIdx.x * 32;
    int tx = threadIdx.x & 31, ty4 = (threadIdx.x >> 5) * 4;
    #pragma unroll
    for (int r = 0; r < 4; r++)
        t[ty4 + r][tx] = W[(size_t)(kb + ty4 + r) * N + nb + tx];
    __syncthreads();
    int txp = p16(tx);
    #pragma unroll
    for (int r = 0; r < 4; r++)
        WT[(size_t)(nb + ty4 + r) * K + kb + txp] = __float2half_rn(t[tx][ty4 + r]);
}

__global__ __launch_bounds__(256) void transpose_kernel(
    const float* __restrict__ W, __half* __restrict__ WT, int K, int N)
{
    __shared__ float t[32][33];
    int kb = blockIdx.y * 32, nb = blockIdx.x * 32;
    int tx = threadIdx.x & 31, ty4 = (threadIdx.x >> 5) * 4;
    #pragma unroll
    for (int r = 0; r < 4; r++)
        t[ty4 + r][tx] = W[(size_t)(kb + ty4 + r) * N + nb + tx];
    __syncthreads();
    int txp = p16(tx);
    #pragma unroll
    for (int r = 0; r < 4; r++)
        WT[(size_t)(nb + ty4 + r) * K + kb + txp] = __float2half_rn(t[tx][ty4 + r]);
}

// ---------------- LayerNorm: warp-per-row, no barriers -> half k16-perm ----------
__global__ __launch_bounds__(256) void ln_kernel(
    const float* __restrict__ x, const float* __restrict__ g,
    const float* __restrict__ b, __half* __restrict__ out)
{
    int w = threadIdx.x >> 5, lane = threadIdx.x & 31;
    int row = blockIdx.x * 8 + w;
    const float4* xr = reinterpret_cast<const float4*>(x + (size_t)row * D_);

    float4 v[8];
    float s = 0.f, ss = 0.f;
    #pragma unroll
    for (int j = 0; j < 8; j++) {
        v[j] = xr[lane + 32 * j];
        s  += v[j].x + v[j].y + v[j].z + v[j].w;
        ss += v[j].x*v[j].x + v[j].y*v[j].y + v[j].z*v[j].z + v[j].w*v[j].w;
    }
    #pragma unroll
    for (int o = 16; o; o >>= 1) {
        s  += __shfl_xor_sync(0xffffffffu, s,  o);
        ss += __shfl_xor_sync(0xffffffffu, ss, o);
    }
    float mean = s * (1.0f / D_);
    float var  = ss * (1.0f / D_) - mean * mean;
    float rstd = rsqrtf(var + 1e-5f);

    const float4* gv = reinterpret_cast<const float4*>(g);
    const float4* bv = reinterpret_cast<const float4*>(b);
    __half* orow = out + (size_t)row * D_;
    #pragma unroll
    for (int j = 0; j < 8; j++) {
        int idx = lane + 32 * j;
        float4 g4 = gv[idx], b4 = bv[idx];
        float o0 = (v[j].x - mean) * rstd * g4.x + b4.x;
        float o1 = (v[j].y - mean) * rstd * g4.y + b4.y;
        float o2 = (v[j].z - mean) * rstd * g4.z + b4.z;
        float o3 = (v[j].w - mean) * rstd * g4.w + b4.w;
        int cbase = idx * 4;
        int pos0 = p16(cbase);
        *reinterpret_cast<__half2*>(orow + pos0)     = __floats2half2_rn(o0, o1);
        *reinterpret_cast<__half2*>(orow + pos0 + 4) = __floats2half2_rn(o2, o3);
    }
}

// ---------------- fp16 mma.sync GEMM: C = A[MxK] @ WT[NxK]^T ---------------------
// 128x128 block tile, 128 threads (4 warps, 2x2), warp tile 64x64, BK=32 halves,
// 3-stage cp.async, LDS.64 fragment loads, stride 48 halves (conflict-free).
// MODE 0: fp32 out (+resid); MODE 1: half k16-perm out; MODE 2: QKV split
//   (cols < vcol0 -> half perm, stride vcol0; cols >= vcol0 -> V^T half
//    vt[batch][dim][t], batch = r / vbatch).
#define SSTR 48
#define HSTAGE (128 * SSTR)
#define GEMM_SMEM (3 * 2 * HSTAGE * 2)      // 73728 bytes

template<bool GELU, int MODE>
__global__ __launch_bounds__(128) void gemm_mma(
    const __half* __restrict__ A, const __half* __restrict__ WT,
    const float* __restrict__ resid, void* __restrict__ Cout,
    __half* __restrict__ vt_out, int vcol0, int vbatch,
    int M, int N, int K)
{
    extern __shared__ __half smh[];
    __half* As = smh;                 // [3][128][SSTR]
    __half* Bs = smh + 3 * HSTAGE;

    int tid = threadIdx.x;
    int wid = tid >> 5, lane = tid & 31;
    int warpM = wid >> 1, warpN = wid & 1;
    int grp = lane >> 2, tig = lane & 3;

    int n0 = blockIdx.x * 128, m0 = blockIdx.y * 128;
    const __half* Ab = A  + (size_t)m0 * K;
    const __half* Bb = WT + (size_t)n0 * K;

    float acc[4][8][4];
    #pragma unroll
    for (int i = 0; i < 4; i++)
        #pragma unroll
        for (int j = 0; j < 8; j++)
            #pragma unroll
            for (int q = 0; q < 4; q++) acc[i][j][q] = 0.f;

    int nk = K >> 5;

    auto load_stage = [&](int st, int kt) {
        int k0 = kt << 5;
        __half* Ast = As + st * HSTAGE;
        __half* Bst = Bs + st * HSTAGE;
        #pragma unroll
        for (int i = 0; i < 4; i++) {
            int idx = tid + i * 128;
            int m = idx >> 2, kc = (idx & 3) * 8;
            cp16(smem_u32(Ast + m * SSTR + kc), Ab + (size_t)m * K + k0 + kc);
            cp16(smem_u32(Bst + m * SSTR + kc), Bb + (size_t)m * K + k0 + kc);
        }
        cp_commit();
    };

    load_stage(0, 0);
    if (nk > 1) load_stage(1, 1);

    for (int kt = 0; kt < nk; kt++) {
        int buf = kt % 3;
        if (kt + 1 < nk) cp_wait<1>(); else cp_wait<0>();
        __syncthreads();
        if (kt + 2 < nk) load_stage((kt + 2) % 3, kt + 2);

        __half* Abuf = As + buf * HSTAGE;
        __half* Bbuf = Bs + buf * HSTAGE;

        #pragma unroll
        for (int ks = 0; ks < 2; ks++) {
            int kof = ks * 16 + 4 * tig;
            uint32_t af[4][4], bf[8][2];
            #pragma unroll
            for (int mt = 0; mt < 4; mt++) {
                int rA = warpM * 64 + mt * 16 + grp;
                uint2 lo = *reinterpret_cast<const uint2*>(Abuf + rA * SSTR + kof);
                uint2 hi = *reinterpret_cast<const uint2*>(Abuf + (rA + 8) * SSTR + kof);
                af[mt][0] = lo.x; af[mt][1] = hi.x;
                af[mt][2] = lo.y; af[mt][3] = hi.y;
            }
            #pragma unroll
            for (int nt = 0; nt < 8; nt++) {
                int rB = warpN * 64 + nt * 8 + grp;
                uint2 bb = *reinterpret_cast<const uint2*>(Bbuf + rB * SSTR + kof);
                bf[nt][0] = bb.x; bf[nt][1] = bb.y;
            }
            #pragma unroll
            for (int mt = 0; mt < 4; mt++)
                #pragma unroll
                for (int nt = 0; nt < 8; nt++)
                    mma16(acc[mt][nt], af[mt], bf[nt]);
        }
    }

    bool vt_region = (MODE == 2) && (n0 >= vcol0);

    #pragma unroll
    for (int mt = 0; mt < 4; mt++) {
        int row = m0 + warpM * 64 + mt * 16 + grp;
        #pragma unroll
        for (int nt = 0; nt < 8; nt++) {
            int col = n0 + warpN * 64 + nt * 8 + 2 * tig;
            #pragma unroll
            for (int half_ = 0; half_ < 2; half_++) {
                int r = row + half_ * 8;
                float v0 = acc[mt][nt][half_ * 2 + 0];
                float v1 = acc[mt][nt][half_ * 2 + 1];
                if (GELU) {
                    v0 = 0.5f * v0 * (1.0f + erff(v0 * 0.70710678118654752f));
                    v1 = 0.5f * v1 * (1.0f + erff(v1 * 0.70710678118654752f));
                }
                if (MODE == 0) {
                    if (resid) {
                        float2 rv = *reinterpret_cast<const float2*>(resid + (size_t)r * N + col);
                        v0 += rv.x; v1 += rv.y;
                    }
                    float* Cf = (float*)Cout;
                    float2 ov = {v0, v1};
                    *reinterpret_cast<float2*>(Cf + (size_t)r * N + col) = ov;
                } else if (MODE == 1 || !vt_region) {
                    int ldo = (MODE == 2) ? vcol0 : N;
                    __half* C16 = (__half*)Cout;
                    *reinterpret_cast<__half2*>(C16 + (size_t)r * ldo + p16(col)) =
                        __floats2half2_rn(v0, v1);
                } else {
                    int dim = col - vcol0;
                    int batch = r / vbatch;
                    int t = r - batch * vbatch;
                    size_t base = ((size_t)batch * (N - vcol0) + dim) * vbatch + t;
                    vt_out[base]          = __float2half_rn(v0);
                    vt_out[base + vbatch] = __float2half_rn(v1);
                }
            }
        }
    }
}

// ---------------- fp16 tensor-core flash attention (online softmax) --------------
// Qh/Kh: half, k16-permuted dims, row strides qld/kld.
// Vt: half V^T  [batch][dim][key], key stride = kv_tokens_per_batch.
// O: half, k16-permuted (GEMM A operand), stride D_.
// CAUSAL: qt reversed (longest CTAs launch first -> LPT schedule).
#define KSH 80
#define VSH 72
#define PSH 80
#define ATTH_HALVES (2 * (64 * KSH + 64 * VSH) + 4 * 16 * PSH)
#define ATTH_BYTES  (ATTH_HALVES * 2)

template<bool CAUSAL>
__global__ __launch_bounds__(128) void attn_h(
    const __half* __restrict__ Qh, const __half* __restrict__ Kh,
    const __half* __restrict__ Vt, __half* __restrict__ O,
    int klen, int qtpb, int kvtpb, int qld, int kld)
{
    extern __shared__ __half smh[];
    int tid = threadIdx.x, w = tid >> 5, lane = tid & 31;
    int grp = lane >> 2, tig = lane & 3;
    int qt = CAUSAL ? (gridDim.x - 1 - blockIdx.x) : blockIdx.x;
    int h = blockIdx.y, b = blockIdx.z;
    int qbase = b * qtpb + qt * 64;

    const int KV_BUF = 64 * KSH + 64 * VSH;
    __half* Ks0 = smh;
    __half* Vs0 = smh + 64 * KSH;
    __half* Ks1 = smh + KV_BUF;
    __half* Vs1 = smh + KV_BUF + 64 * KSH;
    __half* Ps  = smh + 2 * KV_BUF + w * (16 * PSH);

    // ---- stage Q (half, permuted) into Ks0, build scaled A-fragments ----
    for (int i = tid; i < 64 * 8; i += 128) {
        int r = i >> 3, c = (i & 7) * 8;
        *reinterpret_cast<uint4*>(&Ks0[r * KSH + c]) =
            *reinterpret_cast<const uint4*>(&Qh[(size_t)(qbase + r) * qld + h * HD_ + c]);
    }
    __syncthreads();
    uint32_t aq[4][4];
    {
        __half2 sch = __half2half2(__float2half(0.125f));   // exact
        uint32_t sc = *reinterpret_cast<uint32_t*>(&sch);
        int r0 = w * 16 + grp;
        #pragma unroll
        for (int ko = 0; ko < 4; ko++) {
            int base = 16 * ko + 4 * tig;
            uint2 lo = *reinterpret_cast<const uint2*>(&Ks0[r0 * KSH + base]);
            uint2 hi = *reinterpret_cast<const uint2*>(&Ks0[(r0 + 8) * KSH + base]);
            aq[ko][0] = hmul2u(lo.x, sc); aq[ko][1] = hmul2u(hi.x, sc);
            aq[ko][2] = hmul2u(lo.y, sc); aq[ko][3] = hmul2u(hi.y, sc);
        }
    }
    __syncthreads();

    float o[8][4];
    #pragma unroll
    for (int i = 0; i < 8; i++)
        #pragma unroll
        for (int j = 0; j < 4; j++) o[i][j] = 0.f;
    float m0 = -1e30f, m1 = -1e30f, l0 = 0.f, l1 = 0.f;

    int ktiles = klen >> 6;
    if (CAUSAL && qt + 1 < ktiles) ktiles = qt + 1;

    auto load_kv = [&](__half* Ks, __half* Vs, int kt) {
        int kb = kt * 64;
        for (int i = tid; i < 512; i += 128) {
            int r = i >> 3, c = (i & 7) * 8;
            cp16(smem_u32(&Ks[r * KSH + c]),
                 Kh + (size_t)(b * kvtpb + kb + r) * kld + h * HD_ + c);
            cp16(smem_u32(&Vs[r * VSH + c]),
                 Vt + ((size_t)(b * D_ + h * HD_ + r)) * kvtpb + kb + c);
        }
        cp_commit();
    };

    load_kv(Ks0, Vs0, 0);

    for (int kt = 0; kt < ktiles; kt++) {
        int buf = kt & 1;
        __half* Ks = buf ? Ks1 : Ks0;
        __half* Vs = buf ? Vs1 : Vs0;
        if (kt + 1 < ktiles) {
            load_kv(buf ? Ks0 : Ks1, buf ? Vs0 : Vs1, kt + 1);
            cp_wait<1>();
        } else {
            cp_wait<0>();
        }
        __syncthreads();

        // ---- S = Q @ K^T (fp16 k16) ----
        float s[8][4];
        #pragma unroll
        for (int nt = 0; nt < 8; nt++)
            #pragma unroll
            for (int j = 0; j < 4; j++) s[nt][j] = 0.f;

        #pragma unroll
        for (int ko = 0; ko < 4; ko++) {
            int kof = 16 * ko + 4 * tig;
            #pragma unroll
            for (int nt = 0; nt < 8; nt++) {
                int key = nt * 8 + grp;
                uint2 bb = *reinterpret_cast<const uint2*>(&Ks[key * KSH + kof]);
                uint32_t bk[2] = {bb.x, bb.y};
                mma16(s[nt], aq[ko], bk);
            }
        }

        if (CAUSAL && kt == qt) {
            int r0 = qt * 64 + w * 16 + grp;
            #pragma unroll
            for (int nt = 0; nt < 8; nt++) {
                int c = kt * 64 + nt * 8 + 2 * tig;
                if (c     > r0)     s[nt][0] = -1e30f;
                if (c + 1 > r0)     s[nt][1] = -1e30f;
                if (c     > r0 + 8) s[nt][2] = -1e30f;
                if (c + 1 > r0 + 8) s[nt][3] = -1e30f;
            }
        }

        // ---- online softmax ----
        float t0 = -1e30f, t1 = -1e30f;
        #pragma unroll
        for (int nt = 0; nt < 8; nt++) {
            t0 = fmaxf(t0, fmaxf(s[nt][0], s[nt][1]));
            t1 = fmaxf(t1, fmaxf(s[nt][2], s[nt][3]));
        }
        t0 = fmaxf(t0, __shfl_xor_sync(0xffffffffu, t0, 1));
        t0 = fmaxf(t0, __shfl_xor_sync(0xffffffffu, t0, 2));
        t1 = fmaxf(t1, __shfl_xor_sync(0xffffffffu, t1, 1));
        t1 = fmaxf(t1, __shfl_xor_sync(0xffffffffu, t1, 2));
        float nm0 = fmaxf(m0, t0), nm1 = fmaxf(m1, t1);
        float c0 = __expf(m0 - nm0), c1 = __expf(m1 - nm1);
        float ts0 = 0.f, ts1 = 0.f;
        #pragma unroll
        for (int nt = 0; nt < 8; nt++) {
            s[nt][0] = __expf(s[nt][0] - nm0);
            s[nt][1] = __expf(s[nt][1] - nm0);
            s[nt][2] = __expf(s[nt][2] - nm1);
            s[nt][3] = __expf(s[nt][3] - nm1);
            ts0 += s[nt][0] + s[nt][1];
            ts1 += s[nt][2] + s[nt][3];
        }
        ts0 += __shfl_xor_sync(0xffffffffu, ts0, 1);
        ts0 += __shfl_xor_sync(0xffffffffu, ts0, 2);
        ts1 += __shfl_xor_sync(0xffffffffu, ts1, 1);
        ts1 += __shfl_xor_sync(0xffffffffu, ts1, 2);
        l0 = l0 * c0 + ts0;
        l1 = l1 * c1 + ts1;
        m0 = nm0; m1 = nm1;
        #pragma unroll
        for (int nt = 0; nt < 8; nt++) {
            o[nt][0] *= c0; o[nt][1] *= c0;
            o[nt][2] *= c1; o[nt][3] *= c1;
        }

        // ---- P -> half, key-permuted, warp-private smem ----
        #pragma unroll
        for (int nt = 0; nt < 8; nt++) {
            int pos = (nt >> 1) * 16 + 4 * tig + 2 * (nt & 1);
            *reinterpret_cast<__half2*>(&Ps[grp * PSH + pos]) =
                __floats2half2_rn(s[nt][0], s[nt][1]);
            *reinterpret_cast<__half2*>(&Ps[(grp + 8) * PSH + pos]) =
                __floats2half2_rn(s[nt][2], s[nt][3]);
        }
        __syncwarp();

        // ---- O += P @ V (fp16 k16, V^T dim-major smem) ----
        #pragma unroll
        for (int ko = 0; ko < 4; ko++) {
            int kof = 16 * ko + 4 * tig;
            uint2 lo = *reinterpret_cast<const uint2*>(&Ps[grp * PSH + kof]);
            uint2 hi = *reinterpret_cast<const uint2*>(&Ps[(grp + 8) * PSH + kof]);
            uint32_t ap[4] = {lo.x, hi.x, lo.y, hi.y};
            #pragma unroll
            for (int nt2 = 0; nt2 < 8; nt2++) {
                int n = nt2 * 8 + grp;
                uint32_t bv[2];
                bv[0] = *reinterpret_cast<const uint32_t*>(&Vs[n * VSH + 16 * ko + 2 * tig]);
                bv[1] = *reinterpret_cast<const uint32_t*>(&Vs[n * VSH + 16 * ko + 2 * tig + 8]);
                mma16(o[nt2], ap, bv);
            }
        }
        __syncwarp();
        __syncthreads();
    }

    // ---- epilogue: half, k16-permuted ----
    float il0 = 1.0f / l0, il1 = 1.0f / l1;
    int r0 = qbase + w * 16 + grp;
    #pragma unroll
    for (int nt2 = 0; nt2 < 8; nt2++) {
        int col = h * HD_ + nt2 * 8 + 2 * tig;
        int pos = p16(col);
        *reinterpret_cast<__half2*>(O + (size_t)r0 * D_ + pos) =
            __floats2half2_rn(o[nt2][0] * il0, o[nt2][1] * il0);
        *reinterpret_cast<__half2*>(O + (size_t)(r0 + 8) * D_ + pos) =
            __floats2half2_rn(o[nt2][2] * il1, o[nt2][3] * il1);
    }
}

// ---------------- launch ---------------------------------------------------------
extern "C" void kernel_launch(void* const* d_in, const int* in_sizes, int n_in,
                              void* d_out, int out_size)
{
    const float* x         = (const float*)d_in[0];
    const float* neighbors = (const float*)d_in[1];
    const float* sa_ln_g   = (const float*)d_in[2];
    const float* sa_ln_b   = (const float*)d_in[3];
    const float* sa_wq     = (const float*)d_in[4];
    const float* sa_wk     = (const float*)d_in[5];
    const float* sa_wv     = (const float*)d_in[6];
    const float* sa_wo     = (const float*)d_in[7];
    const float* cca_lnq_g = (const float*)d_in[8];
    const float* cca_lnq_b = (const float*)d_in[9];
    const float* cca_lnkv_g= (const float*)d_in[10];
    const float* cca_lnkv_b= (const float*)d_in[11];
    const float* cca_wq    = (const float*)d_in[12];
    const float* cca_wk    = (const float*)d_in[13];
    const float* cca_wv    = (const float*)d_in[14];
    const float* cca_wo    = (const float*)d_in[15];
    const float* ffn_ln_g  = (const float*)d_in[16];
    const float* ffn_ln_b  = (const float*)d_in[17];
    const float* ffn_w1    = (const float*)d_in[18];
    const float* ffn_w2    = (const float*)d_in[19];
    float* out = (float*)d_out;

    __half *h, *kvln, *attn, *ffn, *wt, *qk, *vt, *ccq, *cck, *ccvt;
    float *x1;
    cudaGetSymbolAddress((void**)&h,    g_h);
    cudaGetSymbolAddress((void**)&kvln, g_kvln);
    cudaGetSymbolAddress((void**)&attn, g_attn);
    cudaGetSymbolAddress((void**)&ffn,  g_ffn);
    cudaGetSymbolAddress((void**)&wt,   g_wt);
    cudaGetSymbolAddress((void**)&qk,   g_qk);
    cudaGetSymbolAddress((void**)&vt,   g_vt);
    cudaGetSymbolAddress((void**)&ccq,  g_ccq);
    cudaGetSymbolAddress((void**)&cck,  g_cck);
    cudaGetSymbolAddress((void**)&ccvt, g_ccvt);
    cudaGetSymbolAddress((void**)&x1,   g_x1);

    const size_t MB = 1024 * 1024;
    __half* wt_saqkv = wt + 0 * MB;   // [3072, 1024]
    __half* wt_sao   = wt + 3 * MB;
    __half* wt_ccq   = wt + 4 * MB;
    __half* wt_cckv  = wt + 5 * MB;   // [2048, 1024]
    __half* wt_cco   = wt + 7 * MB;
    __half* wt_f1    = wt + 8 * MB;   // [DFF, D]
    __half* wt_f2    = wt + 12 * MB;  // [D, DFF]

    cudaFuncSetAttribute(attn_h<true >, cudaFuncAttributeMaxDynamicSharedMemorySize, ATTH_BYTES);
    cudaFuncSetAttribute(attn_h<false>, cudaFuncAttributeMaxDynamicSharedMemorySize, ATTH_BYTES);
    cudaFuncSetAttribute((const void*)&gemm_mma<false,0>,
                         cudaFuncAttributeMaxDynamicSharedMemorySize, GEMM_SMEM);
    cudaFuncSetAttribute((const void*)&gemm_mma<false,1>,
                         cudaFuncAttributeMaxDynamicSharedMemorySize, GEMM_SMEM);
    cudaFuncSetAttribute((const void*)&gemm_mma<false,2>,
                         cudaFuncAttributeMaxDynamicSharedMemorySize, GEMM_SMEM);
    cudaFuncSetAttribute((const void*)&gemm_mma<true ,1>,
                         cudaFuncAttributeMaxDynamicSharedMemorySize, GEMM_SMEM);

    // Side stream + events: created ONCE, on the first (uncaptured) call.
    // The capture call then only records/waits events — the documented way to
    // express cross-stream dependencies inside a captured graph.
    static cudaStream_t s1 = nullptr;
    static cudaEvent_t  e0 = nullptr, e1 = nullptr;
    if (s1 == nullptr) {
        cudaStreamCreateWithFlags(&s1, cudaStreamNonBlocking);
        cudaEventCreateWithFlags(&e0, cudaEventDisableTiming);
        cudaEventCreateWithFlags(&e1, cudaEventDisableTiming);
    }

    dim3 blk256(256), blk128(128);

    // ---- batched weight transposes (fp32 -> half, k16-permuted) ----
    TP8 tp;
    tp.src[0] = sa_wq;  tp.dst[0] = wt_saqkv + 0 * MB;
    tp.src[1] = sa_wk;  tp.dst[1] = wt_saqkv + 1 * MB;
    tp.src[2] = sa_wv;  tp.dst[2] = wt_saqkv + 2 * MB;
    tp.src[3] = sa_wo;  tp.dst[3] = wt_sao;
    tp.src[4] = cca_wq; tp.dst[4] = wt_ccq;
    tp.src[5] = cca_wk; tp.dst[5] = wt_cckv + 0 * MB;
    tp.src[6] = cca_wv; tp.dst[6] = wt_cckv + 1 * MB;
    tp.src[7] = cca_wo; tp.dst[7] = wt_cco;
    transpose8_kernel<<<dim3(D_ / 32, D_ / 32, 8), blk256>>>(tp, D_, D_);
    cudaEventRecord(e0, 0);

    // ---- fork: neighbor branch on s1 (independent until CCA attention) ----
    cudaStreamWaitEvent(s1, e0, 0);
    ln_kernel<<<KVTOK_ / 8, blk256, 0, s1>>>(neighbors, cca_lnkv_g, cca_lnkv_b, kvln);
    gemm_mma<false,2><<<dim3(2 * D_ / 128, KVTOK_ / 128), blk128, GEMM_SMEM, s1>>>(
        kvln, wt_cckv, nullptr, cck, ccvt, D_, KV_, KVTOK_, 2 * D_, D_);
    cudaEventRecord(e1, s1);

    // ---- main stream: FFN weight transposes + SA chain ----
    transpose_kernel<<<dim3(DFF_ / 32, D_ / 32), blk256>>>(ffn_w1, wt_f1, D_, DFF_);
    transpose_kernel<<<dim3(D_ / 32, DFF_ / 32), blk256>>>(ffn_w2, wt_f2, DFF_, D_);

    dim3 gProj(D_ / 128, TOK_ / 128);            // (8, 32)
    dim3 gQKV(3 * D_ / 128, TOK_ / 128);         // (24, 32)
    dim3 gFFN1(DFF_ / 128, TOK_ / 128);          // (32, 32)

    ln_kernel<<<TOK_ / 8, blk256>>>(x, sa_ln_g, sa_ln_b, h);
    gemm_mma<false,2><<<gQKV, blk128, GEMM_SMEM>>>(
        h, wt_saqkv, nullptr, qk, vt, 2 * D_, T_, TOK_, 3 * D_, D_);
    attn_h<true><<<dim3(T_ / 64, H_, B_), blk128, ATTH_BYTES>>>(
        qk, qk + D_, vt, attn, T_, T_, T_, 2 * D_, 2 * D_);
    gemm_mma<false,0><<<gProj, blk128, GEMM_SMEM>>>(
        attn, wt_sao, x, x1, nullptr, 0, 0, TOK_, D_, D_);

    // ---- chunked cross-attention (join with neighbor branch) ----
    ln_kernel<<<TOK_ / 8, blk256>>>(x1, cca_lnq_g, cca_lnq_b, h);
    gemm_mma<false,1><<<gProj, blk128, GEMM_SMEM>>>(
        h, wt_ccq, nullptr, ccq, nullptr, 0, 0, TOK_, D_, D_);
    cudaStreamWaitEvent(0, e1, 0);
    attn_h<false><<<dim3(1, H_, NCH_), blk128, ATTH_BYTES>>>(
        ccq, cck, ccvt, attn, KV_, CH_, KV_, D_, D_);
    gemm_mma<false,0><<<gProj, blk128, GEMM_SMEM>>>(
        attn, wt_cco, x1, out, nullptr, 0, 0, TOK_, D_, D_);

    // ---- FFN ----
    ln_kernel<<<TOK_ / 8, blk256>>>(out, ffn_ln_g, ffn_ln_b, h);
    gemm_mma<true ,1><<<gFFN1, blk128, GEMM_SMEM>>>(
        h, wt_f1, nullptr, ffn, nullptr, 0, 0, TOK_, DFF_, D_);
    gemm_mma<false,0><<<gProj, blk128, GEMM_SMEM>>>(
        ffn, wt_f2, out, out, nullptr, 0, 0, TOK_, D_, DFF_);
}

// round 15
// speedup vs baseline: 1.1326x; 1.0308x over previous
#include <cuda_runtime.h>
#include <cuda_fp16.h>
#include <math.h>
#include <cstdint>

// Problem constants (fixed by setup_inputs)
#define B_     2
#define T_     2048
#define D_     1024
#define H_     16
#define HD_    64
#define TOK_   4096      // B*T
#define NCH_   64        // B*NC chunks
#define CH_    64        // chunk_size
#define KV_    256       // K*NL
#define KVTOK_ 16384     // NCH_*KV_
#define DFF_   4096

// ---------------- scratch (static device globals; no allocation) ----------------
__device__ __half g_h   [TOK_  * D_];      // LN out (GEMM A, half k16-perm)
__device__ __half g_kvln[KVTOK_* D_];
__device__ __half g_attn[TOK_  * D_];      // attention out (GEMM A)
__device__ __half g_ffn [TOK_  * DFF_];    // GELU out (GEMM A)
__device__ __half g_wt  [16u * 1024u * 1024u];  // transposed weights (GEMM B)
__device__ __half g_qk  [TOK_  * 2 * D_];  // SA q|k (half, k16-perm)
__device__ __half g_vt  [TOK_  * D_];      // SA V^T: [b][dim][token]
__device__ __half g_ccq [TOK_  * D_];      // CCA q (half perm)
__device__ __half g_cck [KVTOK_* D_];      // CCA k (half perm)
__device__ __half g_ccvt[KVTOK_* D_];      // CCA V^T: [chunk][dim][key]
__device__ float  g_x1  [TOK_  * D_];

// ---------------- helpers ---------------------------------------------------------
__device__ __forceinline__ uint32_t smem_u32(const void* p) {
    uint32_t a;
    asm("{ .reg .u64 t; cvta.to.shared.u64 t, %1; cvt.u32.u64 %0, t; }" : "=r"(a) : "l"(p));
    return a;
}

// k16 permutation: original col c -> packed pos (pairs (2t,2t+1),(2t+8,2t+9) adjacent)
__device__ __forceinline__ int p16(int c) {
    return (c & ~15) + 4 * ((c & 7) >> 1) + 2 * ((c >> 3) & 1) + (c & 1);
}

__device__ __forceinline__ void cp16(uint32_t s, const void* g) {
    asm volatile("cp.async.cg.shared.global [%0], [%1], 16;" :: "r"(s), "l"(g));
}
__device__ __forceinline__ void cp_commit() {
    asm volatile("cp.async.commit_group;" ::: "memory");
}
template<int N>
__device__ __forceinline__ void cp_wait() {
    asm volatile("cp.async.wait_group %0;" :: "n"(N) : "memory");
}

// m16n8k16 fp16 MMA, C(f32) += A*B
__device__ __forceinline__ void mma16(float* c, const uint32_t* a, const uint32_t* b) {
    asm volatile(
        "mma.sync.aligned.m16n8k16.row.col.f32.f16.f16.f32 "
        "{%0,%1,%2,%3}, {%4,%5,%6,%7}, {%8,%9}, {%0,%1,%2,%3};"
        : "+f"(c[0]), "+f"(c[1]), "+f"(c[2]), "+f"(c[3])
        : "r"(a[0]), "r"(a[1]), "r"(a[2]), "r"(a[3]), "r"(b[0]), "r"(b[1]));
}

__device__ __forceinline__ uint32_t hmul2u(uint32_t x, uint32_t s) {
    __half2 a = *reinterpret_cast<__half2*>(&x);
    __half2 b = *reinterpret_cast<__half2*>(&s);
    __half2 r = __hmul2(a, b);
    return *reinterpret_cast<uint32_t*>(&r);
}

// ---------------- batched weight transpose: WT[n, p16(k)] = half(W[k,n]) ---------
struct TP8 { const float* src[8]; __half* dst[8]; };

__global__ __launch_bounds__(256) void transpose8_kernel(TP8 p, int K, int N)
{
    __shared__ float t[32][33];
    const float* W = p.src[blockIdx.z];
    __half* WT = p.dst[blockIdx.z];
    int kb = blockIdx.y * 32, nb = blockIdx.x * 32;
    int tx = threadIdx.x & 31, ty4 = (threadIdx.x >> 5) * 4;
    #pragma unroll
    for (int r = 0; r < 4; r++)
        t[ty4 + r][tx] = W[(size_t)(kb + ty4 + r) * N + nb + tx];
    __syncthreads();
    int txp = p16(tx);
    #pragma unroll
    for (int r = 0; r < 4; r++)
        WT[(size_t)(nb + ty4 + r) * K + kb + txp] = __float2half_rn(t[tx][ty4 + r]);
}

__global__ __launch_bounds__(256) void transpose_kernel(
    const float* __restrict__ W, __half* __restrict__ WT, int K, int N)
{
    __shared__ float t[32][33];
    int kb = blockIdx.y * 32, nb = blockIdx.x * 32;
    int tx = threadIdx.x & 31, ty4 = (threadIdx.x >> 5) * 4;
    #pragma unroll
    for (int r = 0; r < 4; r++)
        t[ty4 + r][tx] = W[(size_t)(kb + ty4 + r) * N + nb + tx];
    __syncthreads();
    int txp = p16(tx);
    #pragma unroll
    for (int r = 0; r < 4; r++)
        WT[(size_t)(nb + ty4 + r) * K + kb + txp] = __float2half_rn(t[tx][ty4 + r]);
}

// ---------------- LayerNorm: warp-per-row, no barriers -> half k16-perm ----------
__global__ __launch_bounds__(256) void ln_kernel(
    const float* __restrict__ x, const float* __restrict__ g,
    const float* __restrict__ b, __half* __restrict__ out)
{
    int w = threadIdx.x >> 5, lane = threadIdx.x & 31;
    int row = blockIdx.x * 8 + w;
    const float4* xr = reinterpret_cast<const float4*>(x + (size_t)row * D_);

    float4 v[8];
    float s = 0.f, ss = 0.f;
    #pragma unroll
    for (int j = 0; j < 8; j++) {
        v[j] = xr[lane + 32 * j];
        s  += v[j].x + v[j].y + v[j].z + v[j].w;
        ss += v[j].x*v[j].x + v[j].y*v[j].y + v[j].z*v[j].z + v[j].w*v[j].w;
    }
    #pragma unroll
    for (int o = 16; o; o >>= 1) {
        s  += __shfl_xor_sync(0xffffffffu, s,  o);
        ss += __shfl_xor_sync(0xffffffffu, ss, o);
    }
    float mean = s * (1.0f / D_);
    float var  = ss * (1.0f / D_) - mean * mean;
    float rstd = rsqrtf(var + 1e-5f);

    const float4* gv = reinterpret_cast<const float4*>(g);
    const float4* bv = reinterpret_cast<const float4*>(b);
    __half* orow = out + (size_t)row * D_;
    #pragma unroll
    for (int j = 0; j < 8; j++) {
        int idx = lane + 32 * j;
        float4 g4 = gv[idx], b4 = bv[idx];
        float o0 = (v[j].x - mean) * rstd * g4.x + b4.x;
        float o1 = (v[j].y - mean) * rstd * g4.y + b4.y;
        float o2 = (v[j].z - mean) * rstd * g4.z + b4.z;
        float o3 = (v[j].w - mean) * rstd * g4.w + b4.w;
        int cbase = idx * 4;
        int pos0 = p16(cbase);
        *reinterpret_cast<__half2*>(orow + pos0)     = __floats2half2_rn(o0, o1);
        *reinterpret_cast<__half2*>(orow + pos0 + 4) = __floats2half2_rn(o2, o3);
    }
}

// ---------------- fp16 mma.sync GEMM: C = A[MxK] @ WT[NxK]^T ---------------------
// 128x128 block tile, 128 threads (4 warps, 2x2), warp tile 64x64, BK=32 halves,
// 3-stage cp.async, LDS.64 fragment loads, stride 48 halves (conflict-free).
// MODE 0: fp32 out (+resid); MODE 1: half k16-perm out; MODE 2: QKV split
//   (cols < vcol0 -> half perm, stride vcol0; cols >= vcol0 -> V^T half
//    vt[batch][dim][t], batch = r / vbatch).
#define SSTR 48
#define HSTAGE (128 * SSTR)
#define GEMM_SMEM (3 * 2 * HSTAGE * 2)      // 73728 bytes

template<bool GELU, int MODE>
__global__ __launch_bounds__(128) void gemm_mma(
    const __half* __restrict__ A, const __half* __restrict__ WT,
    const float* __restrict__ resid, void* __restrict__ Cout,
    __half* __restrict__ vt_out, int vcol0, int vbatch,
    int M, int N, int K)
{
    extern __shared__ __half smh[];
    __half* As = smh;                 // [3][128][SSTR]
    __half* Bs = smh + 3 * HSTAGE;

    int tid = threadIdx.x;
    int wid = tid >> 5, lane = tid & 31;
    int warpM = wid >> 1, warpN = wid & 1;
    int grp = lane >> 2, tig = lane & 3;

    int n0 = blockIdx.x * 128, m0 = blockIdx.y * 128;
    const __half* Ab = A  + (size_t)m0 * K;
    const __half* Bb = WT + (size_t)n0 * K;

    float acc[4][8][4];
    #pragma unroll
    for (int i = 0; i < 4; i++)
        #pragma unroll
        for (int j = 0; j < 8; j++)
            #pragma unroll
            for (int q = 0; q < 4; q++) acc[i][j][q] = 0.f;

    int nk = K >> 5;

    auto load_stage = [&](int st, int kt) {
        int k0 = kt << 5;
        __half* Ast = As + st * HSTAGE;
        __half* Bst = Bs + st * HSTAGE;
        #pragma unroll
        for (int i = 0; i < 4; i++) {
            int idx = tid + i * 128;
            int m = idx >> 2, kc = (idx & 3) * 8;
            cp16(smem_u32(Ast + m * SSTR + kc), Ab + (size_t)m * K + k0 + kc);
            cp16(smem_u32(Bst + m * SSTR + kc), Bb + (size_t)m * K + k0 + kc);
        }
        cp_commit();
    };

    load_stage(0, 0);
    if (nk > 1) load_stage(1, 1);

    for (int kt = 0; kt < nk; kt++) {
        int buf = kt % 3;
        if (kt + 1 < nk) cp_wait<1>(); else cp_wait<0>();
        __syncthreads();
        if (kt + 2 < nk) load_stage((kt + 2) % 3, kt + 2);

        __half* Abuf = As + buf * HSTAGE;
        __half* Bbuf = Bs + buf * HSTAGE;

        #pragma unroll
        for (int ks = 0; ks < 2; ks++) {
            int kof = ks * 16 + 4 * tig;
            uint32_t af[4][4], bf[8][2];
            #pragma unroll
            for (int mt = 0; mt < 4; mt++) {
                int rA = warpM * 64 + mt * 16 + grp;
                uint2 lo = *reinterpret_cast<const uint2*>(Abuf + rA * SSTR + kof);
                uint2 hi = *reinterpret_cast<const uint2*>(Abuf + (rA + 8) * SSTR + kof);
                af[mt][0] = lo.x; af[mt][1] = hi.x;
                af[mt][2] = lo.y; af[mt][3] = hi.y;
            }
            #pragma unroll
            for (int nt = 0; nt < 8; nt++) {
                int rB = warpN * 64 + nt * 8 + grp;
                uint2 bb = *reinterpret_cast<const uint2*>(Bbuf + rB * SSTR + kof);
                bf[nt][0] = bb.x; bf[nt][1] = bb.y;
            }
            #pragma unroll
            for (int mt = 0; mt < 4; mt++)
                #pragma unroll
                for (int nt = 0; nt < 8; nt++)
                    mma16(acc[mt][nt], af[mt], bf[nt]);
        }
    }

    bool vt_region = (MODE == 2) && (n0 >= vcol0);

    #pragma unroll
    for (int mt = 0; mt < 4; mt++) {
        int row = m0 + warpM * 64 + mt * 16 + grp;
        #pragma unroll
        for (int nt = 0; nt < 8; nt++) {
            int col = n0 + warpN * 64 + nt * 8 + 2 * tig;
            #pragma unroll
            for (int half_ = 0; half_ < 2; half_++) {
                int r = row + half_ * 8;
                float v0 = acc[mt][nt][half_ * 2 + 0];
                float v1 = acc[mt][nt][half_ * 2 + 1];
                if (GELU) {
                    v0 = 0.5f * v0 * (1.0f + erff(v0 * 0.70710678118654752f));
                    v1 = 0.5f * v1 * (1.0f + erff(v1 * 0.70710678118654752f));
                }
                if (MODE == 0) {
                    if (resid) {
                        float2 rv = *reinterpret_cast<const float2*>(resid + (size_t)r * N + col);
                        v0 += rv.x; v1 += rv.y;
                    }
                    float* Cf = (float*)Cout;
                    float2 ov = {v0, v1};
                    *reinterpret_cast<float2*>(Cf + (size_t)r * N + col) = ov;
                } else if (MODE == 1 || !vt_region) {
                    int ldo = (MODE == 2) ? vcol0 : N;
                    __half* C16 = (__half*)Cout;
                    *reinterpret_cast<__half2*>(C16 + (size_t)r * ldo + p16(col)) =
                        __floats2half2_rn(v0, v1);
                } else {
                    int dim = col - vcol0;
                    int batch = r / vbatch;
                    int t = r - batch * vbatch;
                    size_t base = ((size_t)batch * (N - vcol0) + dim) * vbatch + t;
                    vt_out[base]          = __float2half_rn(v0);
                    vt_out[base + vbatch] = __float2half_rn(v1);
                }
            }
        }
    }
}

// ---------------- fp16 tensor-core flash attention (online softmax) --------------
// Qh/Kh: half, k16-permuted dims, row strides qld/kld.
// Vt: half V^T  [batch][dim][key], key stride = kv_tokens_per_batch.
// O: half, k16-permuted (GEMM A operand), stride D_.
// CAUSAL: qt reversed (longest CTAs launch first -> LPT schedule).
#define KSH 80
#define VSH 72
#define PSH 80
#define ATTH_HALVES (2 * (64 * KSH + 64 * VSH) + 4 * 16 * PSH)
#define ATTH_BYTES  (ATTH_HALVES * 2)

template<bool CAUSAL>
__global__ __launch_bounds__(128) void attn_h(
    const __half* __restrict__ Qh, const __half* __restrict__ Kh,
    const __half* __restrict__ Vt, __half* __restrict__ O,
    int klen, int qtpb, int kvtpb, int qld, int kld)
{
    extern __shared__ __half smh[];
    int tid = threadIdx.x, w = tid >> 5, lane = tid & 31;
    int grp = lane >> 2, tig = lane & 3;
    int qt = CAUSAL ? (gridDim.x - 1 - blockIdx.x) : blockIdx.x;
    int h = blockIdx.y, b = blockIdx.z;
    int qbase = b * qtpb + qt * 64;

    const int KV_BUF = 64 * KSH + 64 * VSH;
    __half* Ks0 = smh;
    __half* Vs0 = smh + 64 * KSH;
    __half* Ks1 = smh + KV_BUF;
    __half* Vs1 = smh + KV_BUF + 64 * KSH;
    __half* Ps  = smh + 2 * KV_BUF + w * (16 * PSH);

    // ---- stage Q (half, permuted) into Ks0, build scaled A-fragments ----
    for (int i = tid; i < 64 * 8; i += 128) {
        int r = i >> 3, c = (i & 7) * 8;
        *reinterpret_cast<uint4*>(&Ks0[r * KSH + c]) =
            *reinterpret_cast<const uint4*>(&Qh[(size_t)(qbase + r) * qld + h * HD_ + c]);
    }
    __syncthreads();
    uint32_t aq[4][4];
    {
        __half2 sch = __half2half2(__float2half(0.125f));   // exact
        uint32_t sc = *reinterpret_cast<uint32_t*>(&sch);
        int r0 = w * 16 + grp;
        #pragma unroll
        for (int ko = 0; ko < 4; ko++) {
            int base = 16 * ko + 4 * tig;
            uint2 lo = *reinterpret_cast<const uint2*>(&Ks0[r0 * KSH + base]);
            uint2 hi = *reinterpret_cast<const uint2*>(&Ks0[(r0 + 8) * KSH + base]);
            aq[ko][0] = hmul2u(lo.x, sc); aq[ko][1] = hmul2u(hi.x, sc);
            aq[ko][2] = hmul2u(lo.y, sc); aq[ko][3] = hmul2u(hi.y, sc);
        }
    }
    __syncthreads();

    float o[8][4];
    #pragma unroll
    for (int i = 0; i < 8; i++)
        #pragma unroll
        for (int j = 0; j < 4; j++) o[i][j] = 0.f;
    float m0 = -1e30f, m1 = -1e30f, l0 = 0.f, l1 = 0.f;

    int ktiles = klen >> 6;
    if (CAUSAL && qt + 1 < ktiles) ktiles = qt + 1;

    auto load_kv = [&](__half* Ks, __half* Vs, int kt) {
        int kb = kt * 64;
        for (int i = tid; i < 512; i += 128) {
            int r = i >> 3, c = (i & 7) * 8;
            cp16(smem_u32(&Ks[r * KSH + c]),
                 Kh + (size_t)(b * kvtpb + kb + r) * kld + h * HD_ + c);
            cp16(smem_u32(&Vs[r * VSH + c]),
                 Vt + ((size_t)(b * D_ + h * HD_ + r)) * kvtpb + kb + c);
        }
        cp_commit();
    };

    load_kv(Ks0, Vs0, 0);

    for (int kt = 0; kt < ktiles; kt++) {
        int buf = kt & 1;
        __half* Ks = buf ? Ks1 : Ks0;
        __half* Vs = buf ? Vs1 : Vs0;
        if (kt + 1 < ktiles) {
            load_kv(buf ? Ks0 : Ks1, buf ? Vs0 : Vs1, kt + 1);
            cp_wait<1>();
        } else {
            cp_wait<0>();
        }
        __syncthreads();

        // ---- S = Q @ K^T (fp16 k16) ----
        float s[8][4];
        #pragma unroll
        for (int nt = 0; nt < 8; nt++)
            #pragma unroll
            for (int j = 0; j < 4; j++) s[nt][j] = 0.f;

        #pragma unroll
        for (int ko = 0; ko < 4; ko++) {
            int kof = 16 * ko + 4 * tig;
            #pragma unroll
            for (int nt = 0; nt < 8; nt++) {
                int key = nt * 8 + grp;
                uint2 bb = *reinterpret_cast<const uint2*>(&Ks[key * KSH + kof]);
                uint32_t bk[2] = {bb.x, bb.y};
                mma16(s[nt], aq[ko], bk);
            }
        }

        if (CAUSAL && kt == qt) {
            int r0 = qt * 64 + w * 16 + grp;
            #pragma unroll
            for (int nt = 0; nt < 8; nt++) {
                int c = kt * 64 + nt * 8 + 2 * tig;
                if (c     > r0)     s[nt][0] = -1e30f;
                if (c + 1 > r0)     s[nt][1] = -1e30f;
                if (c     > r0 + 8) s[nt][2] = -1e30f;
                if (c + 1 > r0 + 8) s[nt][3] = -1e30f;
            }
        }

        // ---- online softmax ----
        float t0 = -1e30f, t1 = -1e30f;
        #pragma unroll
        for (int nt = 0; nt < 8; nt++) {
            t0 = fmaxf(t0, fmaxf(s[nt][0], s[nt][1]));
            t1 = fmaxf(t1, fmaxf(s[nt][2], s[nt][3]));
        }
        t0 = fmaxf(t0, __shfl_xor_sync(0xffffffffu, t0, 1));
        t0 = fmaxf(t0, __shfl_xor_sync(0xffffffffu, t0, 2));
        t1 = fmaxf(t1, __shfl_xor_sync(0xffffffffu, t1, 1));
        t1 = fmaxf(t1, __shfl_xor_sync(0xffffffffu, t1, 2));
        float nm0 = fmaxf(m0, t0), nm1 = fmaxf(m1, t1);
        float c0 = __expf(m0 - nm0), c1 = __expf(m1 - nm1);
        float ts0 = 0.f, ts1 = 0.f;
        #pragma unroll
        for (int nt = 0; nt < 8; nt++) {
            s[nt][0] = __expf(s[nt][0] - nm0);
            s[nt][1] = __expf(s[nt][1] - nm0);
            s[nt][2] = __expf(s[nt][2] - nm1);
            s[nt][3] = __expf(s[nt][3] - nm1);
            ts0 += s[nt][0] + s[nt][1];
            ts1 += s[nt][2] + s[nt][3];
        }
        ts0 += __shfl_xor_sync(0xffffffffu, ts0, 1);
        ts0 += __shfl_xor_sync(0xffffffffu, ts0, 2);
        ts1 += __shfl_xor_sync(0xffffffffu, ts1, 1);
        ts1 += __shfl_xor_sync(0xffffffffu, ts1, 2);
        l0 = l0 * c0 + ts0;
        l1 = l1 * c1 + ts1;
        m0 = nm0; m1 = nm1;
        #pragma unroll
        for (int nt = 0; nt < 8; nt++) {
            o[nt][0] *= c0; o[nt][1] *= c0;
            o[nt][2] *= c1; o[nt][3] *= c1;
        }

        // ---- P -> half, key-permuted, warp-private smem ----
        #pragma unroll
        for (int nt = 0; nt < 8; nt++) {
            int pos = (nt >> 1) * 16 + 4 * tig + 2 * (nt & 1);
            *reinterpret_cast<__half2*>(&Ps[grp * PSH + pos]) =
                __floats2half2_rn(s[nt][0], s[nt][1]);
            *reinterpret_cast<__half2*>(&Ps[(grp + 8) * PSH + pos]) =
                __floats2half2_rn(s[nt][2], s[nt][3]);
        }
        __syncwarp();

        // ---- O += P @ V (fp16 k16, V^T dim-major smem) ----
        #pragma unroll
        for (int ko = 0; ko < 4; ko++) {
            int kof = 16 * ko + 4 * tig;
            uint2 lo = *reinterpret_cast<const uint2*>(&Ps[grp * PSH + kof]);
            uint2 hi = *reinterpret_cast<const uint2*>(&Ps[(grp + 8) * PSH + kof]);
            uint32_t ap[4] = {lo.x, hi.x, lo.y, hi.y};
            #pragma unroll
            for (int nt2 = 0; nt2 < 8; nt2++) {
                int n = nt2 * 8 + grp;
                uint32_t bv[2];
                bv[0] = *reinterpret_cast<const uint32_t*>(&Vs[n * VSH + 16 * ko + 2 * tig]);
                bv[1] = *reinterpret_cast<const uint32_t*>(&Vs[n * VSH + 16 * ko + 2 * tig + 8]);
                mma16(o[nt2], ap, bv);
            }
        }
        __syncwarp();
        __syncthreads();
    }

    // ---- epilogue: half, k16-permuted ----
    float il0 = 1.0f / l0, il1 = 1.0f / l1;
    int r0 = qbase + w * 16 + grp;
    #pragma unroll
    for (int nt2 = 0; nt2 < 8; nt2++) {
        int col = h * HD_ + nt2 * 8 + 2 * tig;
        int pos = p16(col);
        *reinterpret_cast<__half2*>(O + (size_t)r0 * D_ + pos) =
            __floats2half2_rn(o[nt2][0] * il0, o[nt2][1] * il0);
        *reinterpret_cast<__half2*>(O + (size_t)(r0 + 8) * D_ + pos) =
            __floats2half2_rn(o[nt2][2] * il1, o[nt2][3] * il1);
    }
}

// ---------------- launch ---------------------------------------------------------
extern "C" void kernel_launch(void* const* d_in, const int* in_sizes, int n_in,
                              void* d_out, int out_size)
{
    const float* x         = (const float*)d_in[0];
    const float* neighbors = (const float*)d_in[1];
    const float* sa_ln_g   = (const float*)d_in[2];
    const float* sa_ln_b   = (const float*)d_in[3];
    const float* sa_wq     = (const float*)d_in[4];
    const float* sa_wk     = (const float*)d_in[5];
    const float* sa_wv     = (const float*)d_in[6];
    const float* sa_wo     = (const float*)d_in[7];
    const float* cca_lnq_g = (const float*)d_in[8];
    const float* cca_lnq_b = (const float*)d_in[9];
    const float* cca_lnkv_g= (const float*)d_in[10];
    const float* cca_lnkv_b= (const float*)d_in[11];
    const float* cca_wq    = (const float*)d_in[12];
    const float* cca_wk    = (const float*)d_in[13];
    const float* cca_wv    = (const float*)d_in[14];
    const float* cca_wo    = (const float*)d_in[15];
    const float* ffn_ln_g  = (const float*)d_in[16];
    const float* ffn_ln_b  = (const float*)d_in[17];
    const float* ffn_w1    = (const float*)d_in[18];
    const float* ffn_w2    = (const float*)d_in[19];
    float* out = (float*)d_out;

    __half *h, *kvln, *attn, *ffn, *wt, *qk, *vt, *ccq, *cck, *ccvt;
    float *x1;
    cudaGetSymbolAddress((void**)&h,    g_h);
    cudaGetSymbolAddress((void**)&kvln, g_kvln);
    cudaGetSymbolAddress((void**)&attn, g_attn);
    cudaGetSymbolAddress((void**)&ffn,  g_ffn);
    cudaGetSymbolAddress((void**)&wt,   g_wt);
    cudaGetSymbolAddress((void**)&qk,   g_qk);
    cudaGetSymbolAddress((void**)&vt,   g_vt);
    cudaGetSymbolAddress((void**)&ccq,  g_ccq);
    cudaGetSymbolAddress((void**)&cck,  g_cck);
    cudaGetSymbolAddress((void**)&ccvt, g_ccvt);
    cudaGetSymbolAddress((void**)&x1,   g_x1);

    const size_t MB = 1024 * 1024;
    __half* wt_saqkv = wt + 0 * MB;   // [3072, 1024]
    __half* wt_sao   = wt + 3 * MB;
    __half* wt_ccq   = wt + 4 * MB;
    __half* wt_cckv  = wt + 5 * MB;   // [2048, 1024]
    __half* wt_cco   = wt + 7 * MB;
    __half* wt_f1    = wt + 8 * MB;   // [DFF, D]
    __half* wt_f2    = wt + 12 * MB;  // [D, DFF]

    cudaFuncSetAttribute(attn_h<true >, cudaFuncAttributeMaxDynamicSharedMemorySize, ATTH_BYTES);
    cudaFuncSetAttribute(attn_h<false>, cudaFuncAttributeMaxDynamicSharedMemorySize, ATTH_BYTES);
    cudaFuncSetAttribute((const void*)&gemm_mma<false,0>,
                         cudaFuncAttributeMaxDynamicSharedMemorySize, GEMM_SMEM);
    cudaFuncSetAttribute((const void*)&gemm_mma<false,1>,
                         cudaFuncAttributeMaxDynamicSharedMemorySize, GEMM_SMEM);
    cudaFuncSetAttribute((const void*)&gemm_mma<false,2>,
                         cudaFuncAttributeMaxDynamicSharedMemorySize, GEMM_SMEM);
    cudaFuncSetAttribute((const void*)&gemm_mma<true ,1>,
                         cudaFuncAttributeMaxDynamicSharedMemorySize, GEMM_SMEM);

    // Side stream + events: created ONCE, on the first (uncaptured) call.
    static cudaStream_t s1 = nullptr;
    static cudaEvent_t  e0 = nullptr, e1 = nullptr, e2 = nullptr;
    if (s1 == nullptr) {
        cudaStreamCreateWithFlags(&s1, cudaStreamNonBlocking);
        cudaEventCreateWithFlags(&e0, cudaEventDisableTiming);
        cudaEventCreateWithFlags(&e1, cudaEventDisableTiming);
        cudaEventCreateWithFlags(&e2, cudaEventDisableTiming);
    }

    dim3 blk256(256), blk128(128);

    // ---- s1: neighbor LN (needs no weights) starts immediately ----
    ln_kernel<<<KVTOK_ / 8, blk256, 0, s1>>>(neighbors, cca_lnkv_g, cca_lnkv_b, kvln);

    // ---- main: batched weight transposes (fp32 -> half, k16-permuted) ----
    TP8 tp;
    tp.src[0] = sa_wq;  tp.dst[0] = wt_saqkv + 0 * MB;
    tp.src[1] = sa_wk;  tp.dst[1] = wt_saqkv + 1 * MB;
    tp.src[2] = sa_wv;  tp.dst[2] = wt_saqkv + 2 * MB;
    tp.src[3] = sa_wo;  tp.dst[3] = wt_sao;
    tp.src[4] = cca_wq; tp.dst[4] = wt_ccq;
    tp.src[5] = cca_wk; tp.dst[5] = wt_cckv + 0 * MB;
    tp.src[6] = cca_wv; tp.dst[6] = wt_cckv + 1 * MB;
    tp.src[7] = cca_wo; tp.dst[7] = wt_cco;
    transpose8_kernel<<<dim3(D_ / 32, D_ / 32, 8), blk256>>>(tp, D_, D_);
    cudaEventRecord(e0, 0);

    // ---- s1: KV GEMM (needs wt_cckv), then FFN weight transposes ----
    cudaStreamWaitEvent(s1, e0, 0);
    gemm_mma<false,2><<<dim3(2 * D_ / 128, KVTOK_ / 128), blk128, GEMM_SMEM, s1>>>(
        kvln, wt_cckv, nullptr, cck, ccvt, D_, KV_, KVTOK_, 2 * D_, D_);
    cudaEventRecord(e1, s1);
    transpose_kernel<<<dim3(DFF_ / 32, D_ / 32), blk256, 0, s1>>>(ffn_w1, wt_f1, D_, DFF_);
    transpose_kernel<<<dim3(D_ / 32, DFF_ / 32), blk256, 0, s1>>>(ffn_w2, wt_f2, DFF_, D_);
    cudaEventRecord(e2, s1);

    dim3 gProj(D_ / 128, TOK_ / 128);            // (8, 32)
    dim3 gQKV(3 * D_ / 128, TOK_ / 128);         // (24, 32)
    dim3 gFFN1(DFF_ / 128, TOK_ / 128);          // (32, 32)

    // ---- main: SA chain ----
    ln_kernel<<<TOK_ / 8, blk256>>>(x, sa_ln_g, sa_ln_b, h);
    gemm_mma<false,2><<<gQKV, blk128, GEMM_SMEM>>>(
        h, wt_saqkv, nullptr, qk, vt, 2 * D_, T_, TOK_, 3 * D_, D_);
    attn_h<true><<<dim3(T_ / 64, H_, B_), blk128, ATTH_BYTES>>>(
        qk, qk + D_, vt, attn, T_, T_, T_, 2 * D_, 2 * D_);
    gemm_mma<false,0><<<gProj, blk128, GEMM_SMEM>>>(
        attn, wt_sao, x, x1, nullptr, 0, 0, TOK_, D_, D_);

    // ---- chunked cross-attention (join with neighbor branch) ----
    ln_kernel<<<TOK_ / 8, blk256>>>(x1, cca_lnq_g, cca_lnq_b, h);
    gemm_mma<false,1><<<gProj, blk128, GEMM_SMEM>>>(
        h, wt_ccq, nullptr, ccq, nullptr, 0, 0, TOK_, D_, D_);
    cudaStreamWaitEvent(0, e1, 0);
    attn_h<false><<<dim3(1, H_, NCH_), blk128, ATTH_BYTES>>>(
        ccq, cck, ccvt, attn, KV_, CH_, KV_, D_, D_);
    gemm_mma<false,0><<<gProj, blk128, GEMM_SMEM>>>(
        attn, wt_cco, x1, out, nullptr, 0, 0, TOK_, D_, D_);

    // ---- FFN ----
    ln_kernel<<<TOK_ / 8, blk256>>>(out, ffn_ln_g, ffn_ln_b, h);
    cudaStreamWaitEvent(0, e2, 0);
    gemm_mma<true ,1><<<gFFN1, blk128, GEMM_SMEM>>>(
        h, wt_f1, nullptr, ffn, nullptr, 0, 0, TOK_, DFF_, D_);
    gemm_mma<false,0><<<gProj, blk128, GEMM_SMEM>>>(
        ffn, wt_f2, out, out, nullptr, 0, 0, TOK_, D_, DFF_);
}